// round 9
// baseline (speedup 1.0000x reference)
#include <cuda_runtime.h>
#include <cuda_fp16.h>
#include <cstdint>

// Problem dims
#define NB   2048
#define ND   512
#define NH   64
#define NHID 2048

// Tiling
#define BM   128
#define BN   256
#define BK   64
#define NTHREADS 256
#define NCHUNK 64            // 8 n-tiles * 8 k-tiles

// smem layout (bytes). A resident: 128 rows x 1024B, XOR swizzle = 131072.
// B: 3 stages x (64 k-rows x 512B) XOR swizzle = 98304.
#define OFF_A  0
#define ASZ    131072
#define OFF_B  ASZ
#define BSTG   32768
#define NSTAGE 3
#define OFF_ROWACC (OFF_B + NSTAGE * BSTG)   // 229376
#define SMEM_DYN   (OFF_ROWACC + BM * 4)     // 229888 (fits 227KB limit)

#define WSTRIDE ((size_t)BK * NHID * 2)      // 262144 B: k-chunk advance in g_Wh
#define WWRAP   ((long long)(BN * 2) - 7 * (long long)WSTRIDE)

// fp16 copies + packed epilogue params (device globals; allocation-free)
__device__ __half g_Wh[(size_t)NH * ND * NHID];   // [H][D][HID], n contiguous
__device__ __half g_Xh[(size_t)NB * ND];          // [B][D], k contiguous
__device__ float4 g_pk4[(size_t)NH * (NHID / 2)]; // (b1[2c],b1[2c+1],W2[2c],W2[2c+1])

__device__ __forceinline__ uint32_t smem_u32(const void* p) {
    return (uint32_t)__cvta_generic_to_shared(p);
}
__device__ __forceinline__ void cp16(uint32_t dst, const void* src) {
    asm volatile("cp.async.cg.shared.global [%0], [%1], 16;" :: "r"(dst), "l"(src));
}
__device__ __forceinline__ void cp_commit() {
    asm volatile("cp.async.commit_group;" ::: "memory");
}
__device__ __forceinline__ float lrelu(float v) {
    return (v >= 0.f) ? v : 0.01f * v;
}

// ---------------------------------------------------------------------------
// Converts
// ---------------------------------------------------------------------------
__global__ void convert_w_kernel(const float* __restrict__ W1) {
    size_t i = (size_t)blockIdx.x * blockDim.x + threadIdx.x;
    const size_t n4 = (size_t)NH * ND * NHID / 4;
    if (i >= n4) return;
    float4 v = ((const float4*)W1)[i];
    __half2* d = (__half2*)g_Wh;
    d[2 * i]     = __floats2half2_rn(v.x, v.y);
    d[2 * i + 1] = __floats2half2_rn(v.z, v.w);
}
__global__ void convert_x_kernel(const float* __restrict__ X) {
    size_t i = (size_t)blockIdx.x * blockDim.x + threadIdx.x;
    const size_t n4 = (size_t)NB * ND / 4;
    if (i >= n4) return;
    float4 v = ((const float4*)X)[i];
    __half2* d = (__half2*)g_Xh;
    d[2 * i]     = __floats2half2_rn(v.x, v.y);
    d[2 * i + 1] = __floats2half2_rn(v.z, v.w);
}
__global__ void pack_kernel(const float* __restrict__ b1, const float* __restrict__ W2) {
    int i = blockIdx.x * blockDim.x + threadIdx.x;     // 64 * 1024
    if (i >= NH * (NHID / 2)) return;
    int h = i >> 10, c = i & 1023;
    const float* b = b1 + (size_t)h * NHID + 2 * c;
    const float* w = W2 + (size_t)h * NHID + 2 * c;
    g_pk4[i] = make_float4(b[0], b[1], w[0], w[1]);
}

// ---------------------------------------------------------------------------
// Main fused kernel. CTA = (128-row m-tile, head). 8 warps in 2(M)x4(N),
// warp tile 64x64. A resident; B 3-stage cp.async pipeline (distance 2).
// All smem addresses hoisted to registers (XOR masks are lane-only).
// ---------------------------------------------------------------------------
__global__ void __launch_bounds__(NTHREADS, 1)
mhmlp_main_kernel(const float* __restrict__ b2, float* __restrict__ out)
{
    extern __shared__ char smem[];
    const uint32_t sbase = smem_u32(smem);
    float* rowacc = (float*)(smem + OFF_ROWACC);

    const int tid  = threadIdx.x;
    const int lane = tid & 31;
    const int wid  = tid >> 5;
    const int wm   = wid >> 2;      // 0..1 : 64-row band
    const int wn   = wid & 3;       // 0..3 : 64-col band

    const int mt = blockIdx.x;      // 16 (fast dim -> head weights hot in L2)
    const int h  = blockIdx.y;      // 64
    const int m0 = mt * BM;

    if (tid < BM) rowacc[tid] = 0.f;

    const __half* __restrict__ Wh_h = g_Wh + (size_t)h * ND * NHID;
    const float4* __restrict__ pk_h = g_pk4 + (size_t)h * (NHID / 2);

    // ---- hoisted addressing (masks depend only on lane: (lane&7)<<4) ----
    const uint32_t xmask = ((uint32_t)(lane & 7)) << 4;
    uint32_t baseA[4];
    #pragma unroll
    for (int mi = 0; mi < 4; mi++) {
        int row = wm * 64 + mi * 16 + (lane & 15);
        baseA[mi] = sbase + OFF_A + (uint32_t)(row * 1024);
    }
    uint32_t laneOffA[4];
    #pragma unroll
    for (int ks = 0; ks < 4; ks++)
        laneOffA[ks] = ((uint32_t)(ks * 32 + (lane >> 4) * 16)) ^ xmask;
    uint32_t offBn[4];
    #pragma unroll
    for (int np = 0; np < 4; np++)
        offBn[np] = ((uint32_t)((wn * 64 + np * 16 + (lane >> 4) * 8) * 2)) ^ xmask;
    const uint32_t rowBbase = (uint32_t)((lane & 15) * 512);  // + ks*8192 per slice

    // staging: per-thread fixed dst base + affine i*4096; src is a walking ptr
    const uint32_t dstB0 = (uint32_t)((tid >> 5) * 512)
                         + (((uint32_t)((tid & 31) * 16)) ^ (((uint32_t)((tid >> 5) & 7)) << 4));
    const char* pW = (const char*)Wh_h + (size_t)(tid >> 5) * NHID * 2 + (size_t)(tid & 31) * 16;

    // ---- prologue: stage ALL of A (committed with B chunk 0) ----
    #pragma unroll
    for (int i = 0; i < 32; i++) {               // 8192 segs of 16B
        int t = tid + i * NTHREADS;
        int r = t >> 6, s = t & 63;
        const void* src = g_Xh + (size_t)(m0 + r) * ND + s * 8;
        uint32_t off = (uint32_t)(r * 1024 + s * 16);
        cp16(sbase + OFF_A + (off ^ (((uint32_t)(r & 7)) << 4)), src);
    }

    auto stageB = [&](int cc) {
        const uint32_t base = sbase + OFF_B + (uint32_t)(cc % NSTAGE) * BSTG + dstB0;
        #pragma unroll
        for (int i = 0; i < 8; i++)
            cp16(base + (uint32_t)(i * 4096), pW + (size_t)i * 8 * NHID * 2);
        cp_commit();
        pW += ((cc & 7) == 7) ? WWRAP : (long long)WSTRIDE;
    };

    stageB(0);          // group 0: A + B0
    stageB(1);          // group 1: B1

    float c[4][8][4];
    #pragma unroll
    for (int mi = 0; mi < 4; mi++)
        #pragma unroll
        for (int ni = 0; ni < 8; ni++)
            #pragma unroll
            for (int e = 0; e < 4; e++) c[mi][ni][e] = 0.f;
    float accrow[8] = {0.f,0.f,0.f,0.f,0.f,0.f,0.f,0.f};

    for (int cc = 0; cc < NCHUNK; ++cc) {
        if (cc + 2 < NCHUNK) stageB(cc + 2); else cp_commit();
        asm volatile("cp.async.wait_group 2;" ::: "memory");
        __syncthreads();      // chunk cc data visible

        const uint32_t ktOff = ((uint32_t)(cc & 7)) << 7;   // kt*128
        const uint32_t bB = sbase + OFF_B + (uint32_t)(cc % NSTAGE) * BSTG + rowBbase;

        #pragma unroll
        for (int ks = 0; ks < 4; ks++) {
            uint32_t a[4][4];
            #pragma unroll
            for (int mi = 0; mi < 4; mi++) {
                uint32_t ad = baseA[mi] + laneOffA[ks] + ktOff;
                asm volatile(
                    "ldmatrix.sync.aligned.m8n8.x4.shared.b16 {%0,%1,%2,%3}, [%4];"
                    : "=r"(a[mi][0]), "=r"(a[mi][1]), "=r"(a[mi][2]), "=r"(a[mi][3])
                    : "r"(ad));
            }
            uint32_t bf[8][2];
            #pragma unroll
            for (int np = 0; np < 4; np++) {
                uint32_t ad = bB + (uint32_t)(ks * 8192) + offBn[np];
                uint32_t r0, r1, r2, r3;
                asm volatile(
                    "ldmatrix.sync.aligned.m8n8.x4.trans.shared.b16 {%0,%1,%2,%3}, [%4];"
                    : "=r"(r0), "=r"(r1), "=r"(r2), "=r"(r3) : "r"(ad));
                bf[2 * np][0] = r0;     bf[2 * np][1] = r1;
                bf[2 * np + 1][0] = r2; bf[2 * np + 1][1] = r3;
            }
            #pragma unroll
            for (int mi = 0; mi < 4; mi++)
                #pragma unroll
                for (int ni = 0; ni < 8; ni++) {
                    asm volatile(
                        "mma.sync.aligned.m16n8k16.row.col.f32.f16.f16.f32 "
                        "{%0,%1,%2,%3}, {%4,%5,%6,%7}, {%8,%9}, {%0,%1,%2,%3};"
                        : "+f"(c[mi][ni][0]), "+f"(c[mi][ni][1]),
                          "+f"(c[mi][ni][2]), "+f"(c[mi][ni][3])
                        : "r"(a[mi][0]), "r"(a[mi][1]), "r"(a[mi][2]), "r"(a[mi][3]),
                          "r"(bf[ni][0]), "r"(bf[ni][1]));
                }
        }
        __syncthreads();      // reads of buffer (cc) done before restage (cc+3)

        if ((cc & 7) == 7) {    // K complete -> fused epilogue for this n-tile
            const int nt = cc >> 3;
            #pragma unroll
            for (int ni = 0; ni < 8; ni++) {
                int cidx = nt * (BN / 2) + wn * 32 + ni * 4 + (lane & 3);
                float4 pk = __ldg(&pk_h[cidx]);
                #pragma unroll
                for (int mi = 0; mi < 4; mi++)
                    #pragma unroll
                    for (int e = 0; e < 4; e++) {
                        float bia = (e & 1) ? pk.y : pk.x;
                        float w2v = (e & 1) ? pk.w : pk.z;
                        float p = c[mi][ni][e] + bia;
                        accrow[mi * 2 + (e >> 1)] =
                            fmaf(lrelu(p), w2v, accrow[mi * 2 + (e >> 1)]);
                        c[mi][ni][e] = 0.f;
                    }
            }
        }
    }

    // reduce 4 lanes sharing each row, then across wn warps via smem atomics
    #pragma unroll
    for (int off = 1; off <= 2; off <<= 1)
        #pragma unroll
        for (int j = 0; j < 8; j++)
            accrow[j] += __shfl_xor_sync(0xffffffffu, accrow[j], off);

    if ((lane & 3) == 0) {
        #pragma unroll
        for (int mi = 0; mi < 4; mi++)
            #pragma unroll
            for (int e2 = 0; e2 < 2; e2++) {
                int row = wm * 64 + mi * 16 + e2 * 8 + (lane >> 2);
                atomicAdd(&rowacc[row], accrow[mi * 2 + e2]);
            }
    }
    __syncthreads();
    if (tid < BM) {
        float v = rowacc[tid] + __ldg(&b2[h]);
        out[(size_t)(m0 + tid) * NH + h] = lrelu(v);
    }
}

// ---------------------------------------------------------------------------
extern "C" void kernel_launch(void* const* d_in, const int* in_sizes, int n_in,
                              void* d_out, int out_size) {
    const float* x  = (const float*)d_in[0];   // [2048, 512]
    const float* W1 = (const float*)d_in[1];   // [64, 512, 2048]
    const float* b1 = (const float*)d_in[2];   // [64, 2048]
    const float* W2 = (const float*)d_in[3];   // [64, 2048]
    const float* b2 = (const float*)d_in[4];   // [64]
    float* out = (float*)d_out;                // [2048, 64]
    (void)in_sizes; (void)n_in; (void)out_size;

    cudaFuncSetAttribute(mhmlp_main_kernel,
                         cudaFuncAttributeMaxDynamicSharedMemorySize, SMEM_DYN);

    {
        size_t n4 = (size_t)NH * ND * NHID / 4;
        convert_w_kernel<<<(int)((n4 + 255) / 256), 256>>>(W1);
    }
    {
        size_t n4 = (size_t)NB * ND / 4;
        convert_x_kernel<<<(int)((n4 + 255) / 256), 256>>>(x);
    }
    {
        int n = NH * (NHID / 2);
        pack_kernel<<<(n + 255) / 256, 256>>>(b1, W2);
    }

    dim3 grid(NB / BM, NH);
    mhmlp_main_kernel<<<grid, NTHREADS, SMEM_DYN>>>(b2, out);
}

// round 10
// speedup vs baseline: 1.0346x; 1.0346x over previous
#include <cuda_runtime.h>
#include <cuda_fp16.h>
#include <cstdint>

// Problem dims
#define NB   2048
#define ND   512
#define NH   64
#define NHID 2048

// Tiling
#define BM   128
#define BN   256
#define BK   64
#define NTHREADS 256
#define NCHUNK 64            // 8 n-tiles * 8 k-tiles

// smem layout (bytes). A resident: 128 rows x 1024B, XOR swizzle = 131072.
// B: 3 stages x (64 k-rows x 512B) XOR swizzle = 98304.
#define OFF_A  0
#define ASZ    131072
#define OFF_B  ASZ
#define BSTG   32768
#define NSTAGE 3
#define OFF_ROWACC (OFF_B + NSTAGE * BSTG)   // 229376
#define SMEM_DYN   (OFF_ROWACC + BM * 4)     // 229888

#define WSTRIDE ((size_t)BK * NHID * 2)      // 262144 B: k-chunk advance in g_Wh
#define WWRAP   ((long long)(BN * 2) - 7 * (long long)WSTRIDE)

// fp16 copies + packed epilogue params (device globals; allocation-free)
__device__ __half g_Wh[(size_t)NH * ND * NHID];   // [H][D][HID], n contiguous
__device__ __half g_Xh[(size_t)NB * ND];          // [B][D], k contiguous
__device__ float4 g_pk4[(size_t)NH * (NHID / 2)]; // (b1[2c],b1[2c+1],W2[2c],W2[2c+1])

__device__ __forceinline__ uint32_t smem_u32(const void* p) {
    return (uint32_t)__cvta_generic_to_shared(p);
}
__device__ __forceinline__ void cp16(uint32_t dst, const void* src) {
    asm volatile("cp.async.cg.shared.global [%0], [%1], 16;" :: "r"(dst), "l"(src));
}
__device__ __forceinline__ void cp_commit() {
    asm volatile("cp.async.commit_group;" ::: "memory");
}
__device__ __forceinline__ float lrelu(float v) {
    return (v >= 0.f) ? v : 0.01f * v;
}

// ---------------------------------------------------------------------------
// Converts
// ---------------------------------------------------------------------------
__global__ void convert_w_kernel(const float* __restrict__ W1) {
    size_t i = (size_t)blockIdx.x * blockDim.x + threadIdx.x;
    const size_t n4 = (size_t)NH * ND * NHID / 4;
    if (i >= n4) return;
    float4 v = ((const float4*)W1)[i];
    __half2* d = (__half2*)g_Wh;
    d[2 * i]     = __floats2half2_rn(v.x, v.y);
    d[2 * i + 1] = __floats2half2_rn(v.z, v.w);
}
__global__ void convert_x_kernel(const float* __restrict__ X) {
    size_t i = (size_t)blockIdx.x * blockDim.x + threadIdx.x;
    const size_t n4 = (size_t)NB * ND / 4;
    if (i >= n4) return;
    float4 v = ((const float4*)X)[i];
    __half2* d = (__half2*)g_Xh;
    d[2 * i]     = __floats2half2_rn(v.x, v.y);
    d[2 * i + 1] = __floats2half2_rn(v.z, v.w);
}
__global__ void pack_kernel(const float* __restrict__ b1, const float* __restrict__ W2) {
    int i = blockIdx.x * blockDim.x + threadIdx.x;     // 64 * 1024
    if (i >= NH * (NHID / 2)) return;
    int h = i >> 10, c = i & 1023;
    const float* b = b1 + (size_t)h * NHID + 2 * c;
    const float* w = W2 + (size_t)h * NHID + 2 * c;
    g_pk4[i] = make_float4(b[0], b[1], w[0], w[1]);
}

// ---------------------------------------------------------------------------
// Main fused kernel. CTA = (128-row m-tile, head). 8 warps in 2(M)x4(N),
// warp tile 64x64. A resident; B 3-stage cp.async pipeline.
// ONE barrier per chunk: wait -> BAR -> stage(cc+2) -> compute(cc).
// B fragments double-buffered in registers (LDSM hidden under MMA stream).
// ---------------------------------------------------------------------------
__global__ void __launch_bounds__(NTHREADS, 1)
mhmlp_main_kernel(const float* __restrict__ b2, float* __restrict__ out)
{
    extern __shared__ char smem[];
    const uint32_t sbase = smem_u32(smem);
    float* rowacc = (float*)(smem + OFF_ROWACC);

    const int tid  = threadIdx.x;
    const int lane = tid & 31;
    const int wid  = tid >> 5;
    const int wm   = wid >> 2;      // 0..1 : 64-row band
    const int wn   = wid & 3;       // 0..3 : 64-col band

    const int mt = blockIdx.x;      // 16 (fast dim -> head weights hot in L2)
    const int h  = blockIdx.y;      // 64
    const int m0 = mt * BM;

    if (tid < BM) rowacc[tid] = 0.f;

    const __half* __restrict__ Wh_h = g_Wh + (size_t)h * ND * NHID;
    const float4* __restrict__ pk_h = g_pk4 + (size_t)h * (NHID / 2);

    // ---- hoisted addressing (masks depend only on lane: (lane&7)<<4) ----
    const uint32_t xmask = ((uint32_t)(lane & 7)) << 4;
    uint32_t baseA[4];
    #pragma unroll
    for (int mi = 0; mi < 4; mi++) {
        int row = wm * 64 + mi * 16 + (lane & 15);
        baseA[mi] = sbase + OFF_A + (uint32_t)(row * 1024);
    }
    uint32_t laneOffA[4];
    #pragma unroll
    for (int ks = 0; ks < 4; ks++)
        laneOffA[ks] = ((uint32_t)(ks * 32 + (lane >> 4) * 16)) ^ xmask;
    uint32_t offBn[4];
    #pragma unroll
    for (int np = 0; np < 4; np++)
        offBn[np] = ((uint32_t)((wn * 64 + np * 16 + (lane >> 4) * 8) * 2)) ^ xmask;
    const uint32_t rowBbase = (uint32_t)((lane & 15) * 512);  // + ks*8192 per slice

    // staging: per-thread fixed dst base + affine i*4096; src is a walking ptr
    const uint32_t dstB0 = (uint32_t)((tid >> 5) * 512)
                         + (((uint32_t)((tid & 31) * 16)) ^ (((uint32_t)((tid >> 5) & 7)) << 4));
    const char* pW = (const char*)Wh_h + (size_t)(tid >> 5) * NHID * 2 + (size_t)(tid & 31) * 16;

    // ---- prologue: stage ALL of A (committed with B chunk 0) ----
    #pragma unroll
    for (int i = 0; i < 32; i++) {               // 8192 segs of 16B
        int t = tid + i * NTHREADS;
        int r = t >> 6, s = t & 63;
        const void* src = g_Xh + (size_t)(m0 + r) * ND + s * 8;
        uint32_t off = (uint32_t)(r * 1024 + s * 16);
        cp16(sbase + OFF_A + (off ^ (((uint32_t)(r & 7)) << 4)), src);
    }

    auto stageB = [&](int cc) {
        const uint32_t base = sbase + OFF_B + (uint32_t)(cc % NSTAGE) * BSTG + dstB0;
        #pragma unroll
        for (int i = 0; i < 8; i++)
            cp16(base + (uint32_t)(i * 4096), pW + (size_t)i * 8 * NHID * 2);
        cp_commit();
        pW += ((cc & 7) == 7) ? WWRAP : (long long)WSTRIDE;
    };

    stageB(0);          // group 0: A + B0
    stageB(1);          // group 1: B1

    float c[4][8][4];
    #pragma unroll
    for (int mi = 0; mi < 4; mi++)
        #pragma unroll
        for (int ni = 0; ni < 8; ni++)
            #pragma unroll
            for (int e = 0; e < 4; e++) c[mi][ni][e] = 0.f;
    float accrow[8] = {0.f,0.f,0.f,0.f,0.f,0.f,0.f,0.f};

    for (int cc = 0; cc < NCHUNK; ++cc) {
        asm volatile("cp.async.wait_group 1;" ::: "memory");
        __syncthreads();      // chunk cc visible; all reads of buf (cc-1)%3 done

        if (cc + 2 < NCHUNK) stageB(cc + 2); else cp_commit();

        const uint32_t ktOff = ((uint32_t)(cc & 7)) << 7;   // kt*128
        const uint32_t bB = sbase + OFF_B + (uint32_t)(cc % NSTAGE) * BSTG + rowBbase;

        // B fragments double-buffered across k-slices
        uint32_t bf[2][8][2];
        {   // preload slice 0
            #pragma unroll
            for (int np = 0; np < 4; np++) {
                uint32_t ad = bB + offBn[np];
                uint32_t r0, r1, r2, r3;
                asm volatile(
                    "ldmatrix.sync.aligned.m8n8.x4.trans.shared.b16 {%0,%1,%2,%3}, [%4];"
                    : "=r"(r0), "=r"(r1), "=r"(r2), "=r"(r3) : "r"(ad));
                bf[0][2 * np][0] = r0;     bf[0][2 * np][1] = r1;
                bf[0][2 * np + 1][0] = r2; bf[0][2 * np + 1][1] = r3;
            }
        }

        #pragma unroll
        for (int ks = 0; ks < 4; ks++) {
            const int cur = ks & 1, nxt = cur ^ 1;
            uint32_t a[4][4];
            #pragma unroll
            for (int mi = 0; mi < 4; mi++) {
                uint32_t ad = baseA[mi] + laneOffA[ks] + ktOff;
                asm volatile(
                    "ldmatrix.sync.aligned.m8n8.x4.shared.b16 {%0,%1,%2,%3}, [%4];"
                    : "=r"(a[mi][0]), "=r"(a[mi][1]), "=r"(a[mi][2]), "=r"(a[mi][3])
                    : "r"(ad));
            }
            if (ks < 3) {     // prefetch B slice ks+1 under the MMA stream
                #pragma unroll
                for (int np = 0; np < 4; np++) {
                    uint32_t ad = bB + (uint32_t)((ks + 1) * 8192) + offBn[np];
                    uint32_t r0, r1, r2, r3;
                    asm volatile(
                        "ldmatrix.sync.aligned.m8n8.x4.trans.shared.b16 {%0,%1,%2,%3}, [%4];"
                        : "=r"(r0), "=r"(r1), "=r"(r2), "=r"(r3) : "r"(ad));
                    bf[nxt][2 * np][0] = r0;     bf[nxt][2 * np][1] = r1;
                    bf[nxt][2 * np + 1][0] = r2; bf[nxt][2 * np + 1][1] = r3;
                }
            }
            #pragma unroll
            for (int mi = 0; mi < 4; mi++)
                #pragma unroll
                for (int ni = 0; ni < 8; ni++) {
                    asm volatile(
                        "mma.sync.aligned.m16n8k16.row.col.f32.f16.f16.f32 "
                        "{%0,%1,%2,%3}, {%4,%5,%6,%7}, {%8,%9}, {%0,%1,%2,%3};"
                        : "+f"(c[mi][ni][0]), "+f"(c[mi][ni][1]),
                          "+f"(c[mi][ni][2]), "+f"(c[mi][ni][3])
                        : "r"(a[mi][0]), "r"(a[mi][1]), "r"(a[mi][2]), "r"(a[mi][3]),
                          "r"(bf[cur][ni][0]), "r"(bf[cur][ni][1]));
                }
        }

        if ((cc & 7) == 7) {    // K complete -> fused epilogue for this n-tile
            const int nt = cc >> 3;
            #pragma unroll
            for (int ni = 0; ni < 8; ni++) {
                int cidx = nt * (BN / 2) + wn * 32 + ni * 4 + (lane & 3);
                float4 pk = __ldg(&pk_h[cidx]);
                #pragma unroll
                for (int mi = 0; mi < 4; mi++)
                    #pragma unroll
                    for (int e = 0; e < 4; e++) {
                        float bia = (e & 1) ? pk.y : pk.x;
                        float w2v = (e & 1) ? pk.w : pk.z;
                        float p = c[mi][ni][e] + bia;
                        accrow[mi * 2 + (e >> 1)] =
                            fmaf(lrelu(p), w2v, accrow[mi * 2 + (e >> 1)]);
                        c[mi][ni][e] = 0.f;
                    }
            }
        }
    }

    // reduce 4 lanes sharing each row, then across wn warps via smem atomics
    #pragma unroll
    for (int off = 1; off <= 2; off <<= 1)
        #pragma unroll
        for (int j = 0; j < 8; j++)
            accrow[j] += __shfl_xor_sync(0xffffffffu, accrow[j], off);

    __syncthreads();   // ensure rowacc zero-init visible & mainloop fully done
    if ((lane & 3) == 0) {
        #pragma unroll
        for (int mi = 0; mi < 4; mi++)
            #pragma unroll
            for (int e2 = 0; e2 < 2; e2++) {
                int row = wm * 64 + mi * 16 + e2 * 8 + (lane >> 2);
                atomicAdd(&rowacc[row], accrow[mi * 2 + e2]);
            }
    }
    __syncthreads();
    if (tid < BM) {
        float v = rowacc[tid] + __ldg(&b2[h]);
        out[(size_t)(m0 + tid) * NH + h] = lrelu(v);
    }
}

// ---------------------------------------------------------------------------
extern "C" void kernel_launch(void* const* d_in, const int* in_sizes, int n_in,
                              void* d_out, int out_size) {
    const float* x  = (const float*)d_in[0];   // [2048, 512]
    const float* W1 = (const float*)d_in[1];   // [64, 512, 2048]
    const float* b1 = (const float*)d_in[2];   // [64, 2048]
    const float* W2 = (const float*)d_in[3];   // [64, 2048]
    const float* b2 = (const float*)d_in[4];   // [64]
    float* out = (float*)d_out;                // [2048, 64]
    (void)in_sizes; (void)n_in; (void)out_size;

    cudaFuncSetAttribute(mhmlp_main_kernel,
                         cudaFuncAttributeMaxDynamicSharedMemorySize, SMEM_DYN);

    {
        size_t n4 = (size_t)NH * ND * NHID / 4;
        convert_w_kernel<<<(int)((n4 + 255) / 256), 256>>>(W1);
    }
    {
        size_t n4 = (size_t)NB * ND / 4;
        convert_x_kernel<<<(int)((n4 + 255) / 256), 256>>>(x);
    }
    {
        int n = NH * (NHID / 2);
        pack_kernel<<<(n + 255) / 256, 256>>>(b1, W2);
    }

    dim3 grid(NB / BM, NH);
    mhmlp_main_kernel<<<grid, NTHREADS, SMEM_DYN>>>(b2, out);
}

// round 11
// speedup vs baseline: 1.1592x; 1.1204x over previous
#include <cuda_runtime.h>
#include <cuda_fp16.h>
#include <cstdint>

// Problem dims
#define NB   2048
#define ND   512
#define NH   64
#define NHID 2048

// Tiling
#define BM   128
#define BN   256            // full n-tile; each warp-group owns a 128 half
#define BK   64
#define NTHREADS 256
#define NCHUNK 64           // 8 n-tiles * 8 k-tiles

// smem layout (bytes). A resident: 128 rows x 1024B, XOR swizzle = 131072.
// B: 2 groups x 3 stages x (64 k-rows x 256B) = 98304.
#define OFF_A  0
#define ASZ    131072
#define OFF_B  ASZ
#define BSTG_G 16384
#define GSTRIDE (3 * BSTG_G)                 // 49152 per group
#define NSTAGE 3
#define OFF_ROWACC (OFF_B + 2 * GSTRIDE)     // 229376
#define SMEM_DYN   (OFF_ROWACC + BM * 4)     // 229888

#define WSTRIDE ((size_t)BK * NHID * 2)      // 262144 B: k-chunk advance in g_Wh
#define WWRAP   ((long long)(BN * 2) - 7 * (long long)WSTRIDE)

// fp16 copies + packed epilogue params (device globals; allocation-free)
__device__ __half g_Wh[(size_t)NH * ND * NHID];   // [H][D][HID], n contiguous
__device__ __half g_Xh[(size_t)NB * ND];          // [B][D], k contiguous
__device__ float4 g_pk4[(size_t)NH * (NHID / 2)]; // (b1[2c],b1[2c+1],W2[2c],W2[2c+1])

__device__ __forceinline__ uint32_t smem_u32(const void* p) {
    return (uint32_t)__cvta_generic_to_shared(p);
}
__device__ __forceinline__ void cp16(uint32_t dst, const void* src) {
    asm volatile("cp.async.cg.shared.global [%0], [%1], 16;" :: "r"(dst), "l"(src));
}
__device__ __forceinline__ void cp_commit() {
    asm volatile("cp.async.commit_group;" ::: "memory");
}
__device__ __forceinline__ void gbar(int id) {
    asm volatile("bar.sync %0, 128;" :: "r"(id) : "memory");
}
__device__ __forceinline__ float lrelu(float v) {
    return (v >= 0.f) ? v : 0.01f * v;
}

// ---------------------------------------------------------------------------
// Converts
// ---------------------------------------------------------------------------
__global__ void convert_w_kernel(const float* __restrict__ W1) {
    size_t i = (size_t)blockIdx.x * blockDim.x + threadIdx.x;
    const size_t n4 = (size_t)NH * ND * NHID / 4;
    if (i >= n4) return;
    float4 v = ((const float4*)W1)[i];
    __half2* d = (__half2*)g_Wh;
    d[2 * i]     = __floats2half2_rn(v.x, v.y);
    d[2 * i + 1] = __floats2half2_rn(v.z, v.w);
}
__global__ void convert_x_kernel(const float* __restrict__ X) {
    size_t i = (size_t)blockIdx.x * blockDim.x + threadIdx.x;
    const size_t n4 = (size_t)NB * ND / 4;
    if (i >= n4) return;
    float4 v = ((const float4*)X)[i];
    __half2* d = (__half2*)g_Xh;
    d[2 * i]     = __floats2half2_rn(v.x, v.y);
    d[2 * i + 1] = __floats2half2_rn(v.z, v.w);
}
__global__ void pack_kernel(const float* __restrict__ b1, const float* __restrict__ W2) {
    int i = blockIdx.x * blockDim.x + threadIdx.x;     // 64 * 1024
    if (i >= NH * (NHID / 2)) return;
    int h = i >> 10, c = i & 1023;
    const float* b = b1 + (size_t)h * NHID + 2 * c;
    const float* w = W2 + (size_t)h * NHID + 2 * c;
    g_pk4[i] = make_float4(b[0], b[1], w[0], w[1]);
}

// ---------------------------------------------------------------------------
// Main fused kernel. CTA = (128-row m-tile, head). TWO independent warp
// groups of 4 (one warp/SMSP each) share resident A but run private B
// pipelines + private named barriers over opposite n-halves -> one group's
// MMA stream covers the other's barrier/LDSM/staging overhead.
// ---------------------------------------------------------------------------
__global__ void __launch_bounds__(NTHREADS, 1)
mhmlp_main_kernel(const float* __restrict__ b2, float* __restrict__ out)
{
    extern __shared__ char smem[];
    const uint32_t sbase = smem_u32(smem);
    float* rowacc = (float*)(smem + OFF_ROWACC);

    const int tid  = threadIdx.x;
    const int lane = tid & 31;
    const int wid  = tid >> 5;
    const int g    = wid >> 2;      // warp group 0/1 (n-half)
    const int w    = wid & 3;       // warp within group (SMSP index)
    const int wm   = w >> 1;        // 0..1 : 64-row band
    const int wn   = w & 1;         // 0..1 : 64-col band within 128-col half

    const int mt = blockIdx.x;      // 16 (fast dim -> head weights hot in L2)
    const int h  = blockIdx.y;      // 64
    const int m0 = mt * BM;

    if (tid < BM) rowacc[tid] = 0.f;

    const __half* __restrict__ Wh_h = g_Wh + (size_t)h * ND * NHID;
    const float4* __restrict__ pk_h = g_pk4 + (size_t)h * (NHID / 2);

    // ---- hoisted addressing ----
    const uint32_t xmask = ((uint32_t)(lane & 7)) << 4;
    uint32_t baseA[4];
    #pragma unroll
    for (int mi = 0; mi < 4; mi++) {
        int row = wm * 64 + mi * 16 + (lane & 15);
        baseA[mi] = sbase + OFF_A + (uint32_t)(row * 1024);
    }
    uint32_t laneOffA[4];
    #pragma unroll
    for (int ks = 0; ks < 4; ks++)
        laneOffA[ks] = ((uint32_t)(ks * 32 + (lane >> 4) * 16)) ^ xmask;
    uint32_t offBn[4];
    #pragma unroll
    for (int np = 0; np < 4; np++)
        offBn[np] = ((uint32_t)((wn * 64 + np * 16 + (lane >> 4) * 8) * 2)) ^ xmask;
    const uint32_t rowBbase = (uint32_t)((lane & 15) * 256);  // 256B rows

    // staging (per group: 128 threads stage 64 rows x 256B)
    const int t128 = tid & 127;
    const int r0 = t128 >> 4;            // 0..7
    const int sseg = t128 & 15;          // 0..15
    const uint32_t dstB0 = (uint32_t)(r0 * 256)
                         + (((uint32_t)(sseg * 16)) ^ (((uint32_t)r0) << 4));
    const char* pW = (const char*)Wh_h + (size_t)r0 * NHID * 2
                   + (size_t)sseg * 16 + (size_t)g * 128 * 2;
    const uint32_t gB = sbase + OFF_B + (uint32_t)g * GSTRIDE;

    // ---- prologue: stage ALL of A (all 256 threads), own commit group ----
    #pragma unroll
    for (int i = 0; i < 32; i++) {               // 8192 segs of 16B
        int t = tid + i * NTHREADS;
        int r = t >> 6, s = t & 63;
        const void* src = g_Xh + (size_t)(m0 + r) * ND + s * 8;
        uint32_t off = (uint32_t)(r * 1024 + s * 16);
        cp16(sbase + OFF_A + (off ^ (((uint32_t)(r & 7)) << 4)), src);
    }
    cp_commit();     // group [A]

    auto stageB = [&](int cc) {
        const uint32_t base = gB + (uint32_t)(cc % NSTAGE) * BSTG_G + dstB0;
        #pragma unroll
        for (int i = 0; i < 8; i++)              // rows r0 + 8i
            cp16(base + (uint32_t)(i * 2048), pW + (size_t)i * 8 * NHID * 2);
        cp_commit();
        pW += ((cc & 7) == 7) ? WWRAP : (long long)WSTRIDE;
    };

    stageB(0);       // group [B0]
    stageB(1);       // group [B1]
    asm volatile("cp.async.wait_group 2;" ::: "memory");   // A done
    __syncthreads();                                        // A visible to all

    float c[4][8][4];
    #pragma unroll
    for (int mi = 0; mi < 4; mi++)
        #pragma unroll
        for (int ni = 0; ni < 8; ni++)
            #pragma unroll
            for (int e = 0; e < 4; e++) c[mi][ni][e] = 0.f;
    float accrow[8] = {0.f,0.f,0.f,0.f,0.f,0.f,0.f,0.f};

    for (int cc = 0; cc < NCHUNK; ++cc) {
        asm volatile("cp.async.wait_group 1;" ::: "memory");
        gbar(1 + g);        // group-private barrier: chunk cc visible in-group

        if (cc + 2 < NCHUNK) stageB(cc + 2); else cp_commit();

        const uint32_t ktOff = ((uint32_t)(cc & 7)) << 7;   // kt*128 bytes
        const uint32_t bB = gB + (uint32_t)(cc % NSTAGE) * BSTG_G + rowBbase;

        uint32_t bf[2][8][2];
        {   // preload slice 0
            #pragma unroll
            for (int np = 0; np < 4; np++) {
                uint32_t ad = bB + offBn[np];
                uint32_t q0, q1, q2, q3;
                asm volatile(
                    "ldmatrix.sync.aligned.m8n8.x4.trans.shared.b16 {%0,%1,%2,%3}, [%4];"
                    : "=r"(q0), "=r"(q1), "=r"(q2), "=r"(q3) : "r"(ad));
                bf[0][2 * np][0] = q0;     bf[0][2 * np][1] = q1;
                bf[0][2 * np + 1][0] = q2; bf[0][2 * np + 1][1] = q3;
            }
        }

        #pragma unroll
        for (int ks = 0; ks < 4; ks++) {
            const int cur = ks & 1, nxt = cur ^ 1;
            uint32_t a[4][4];
            #pragma unroll
            for (int mi = 0; mi < 4; mi++) {
                uint32_t ad = baseA[mi] + laneOffA[ks] + ktOff;
                asm volatile(
                    "ldmatrix.sync.aligned.m8n8.x4.shared.b16 {%0,%1,%2,%3}, [%4];"
                    : "=r"(a[mi][0]), "=r"(a[mi][1]), "=r"(a[mi][2]), "=r"(a[mi][3])
                    : "r"(ad));
            }
            if (ks < 3) {     // prefetch B slice ks+1 under the MMA stream
                #pragma unroll
                for (int np = 0; np < 4; np++) {
                    uint32_t ad = bB + (uint32_t)((ks + 1) * 4096) + offBn[np];
                    uint32_t q0, q1, q2, q3;
                    asm volatile(
                        "ldmatrix.sync.aligned.m8n8.x4.trans.shared.b16 {%0,%1,%2,%3}, [%4];"
                        : "=r"(q0), "=r"(q1), "=r"(q2), "=r"(q3) : "r"(ad));
                    bf[nxt][2 * np][0] = q0;     bf[nxt][2 * np][1] = q1;
                    bf[nxt][2 * np + 1][0] = q2; bf[nxt][2 * np + 1][1] = q3;
                }
            }
            #pragma unroll
            for (int mi = 0; mi < 4; mi++)
                #pragma unroll
                for (int ni = 0; ni < 8; ni++) {
                    asm volatile(
                        "mma.sync.aligned.m16n8k16.row.col.f32.f16.f16.f32 "
                        "{%0,%1,%2,%3}, {%4,%5,%6,%7}, {%8,%9}, {%0,%1,%2,%3};"
                        : "+f"(c[mi][ni][0]), "+f"(c[mi][ni][1]),
                          "+f"(c[mi][ni][2]), "+f"(c[mi][ni][3])
                        : "r"(a[mi][0]), "r"(a[mi][1]), "r"(a[mi][2]), "r"(a[mi][3]),
                          "r"(bf[cur][ni][0]), "r"(bf[cur][ni][1]));
                }
        }

        if ((cc & 7) == 7) {    // K complete -> fused epilogue for this n-tile
            const int nt = cc >> 3;
            #pragma unroll
            for (int ni = 0; ni < 8; ni++) {
                int cidx = nt * 128 + g * 64 + wn * 32 + ni * 4 + (lane & 3);
                float4 pk = __ldg(&pk_h[cidx]);
                #pragma unroll
                for (int mi = 0; mi < 4; mi++)
                    #pragma unroll
                    for (int e = 0; e < 4; e++) {
                        float bia = (e & 1) ? pk.y : pk.x;
                        float w2v = (e & 1) ? pk.w : pk.z;
                        float p = c[mi][ni][e] + bia;
                        accrow[mi * 2 + (e >> 1)] =
                            fmaf(lrelu(p), w2v, accrow[mi * 2 + (e >> 1)]);
                        c[mi][ni][e] = 0.f;
                    }
            }
        }
    }

    // reduce 4 lanes sharing each row, then across warps/groups via smem atomics
    #pragma unroll
    for (int off = 1; off <= 2; off <<= 1)
        #pragma unroll
        for (int j = 0; j < 8; j++)
            accrow[j] += __shfl_xor_sync(0xffffffffu, accrow[j], off);

    __syncthreads();   // rowacc zero-init visible; both groups done
    if ((lane & 3) == 0) {
        #pragma unroll
        for (int mi = 0; mi < 4; mi++)
            #pragma unroll
            for (int e2 = 0; e2 < 2; e2++) {
                int row = wm * 64 + mi * 16 + e2 * 8 + (lane >> 2);
                atomicAdd(&rowacc[row], accrow[mi * 2 + e2]);
            }
    }
    __syncthreads();
    if (tid < BM) {
        float v = rowacc[tid] + __ldg(&b2[h]);
        out[(size_t)(m0 + tid) * NH + h] = lrelu(v);
    }
}

// ---------------------------------------------------------------------------
extern "C" void kernel_launch(void* const* d_in, const int* in_sizes, int n_in,
                              void* d_out, int out_size) {
    const float* x  = (const float*)d_in[0];   // [2048, 512]
    const float* W1 = (const float*)d_in[1];   // [64, 512, 2048]
    const float* b1 = (const float*)d_in[2];   // [64, 2048]
    const float* W2 = (const float*)d_in[3];   // [64, 2048]
    const float* b2 = (const float*)d_in[4];   // [64]
    float* out = (float*)d_out;                // [2048, 64]
    (void)in_sizes; (void)n_in; (void)out_size;

    cudaFuncSetAttribute(mhmlp_main_kernel,
                         cudaFuncAttributeMaxDynamicSharedMemorySize, SMEM_DYN);

    {
        size_t n4 = (size_t)NH * ND * NHID / 4;
        convert_w_kernel<<<(int)((n4 + 255) / 256), 256>>>(W1);
    }
    {
        size_t n4 = (size_t)NB * ND / 4;
        convert_x_kernel<<<(int)((n4 + 255) / 256), 256>>>(x);
    }
    {
        int n = NH * (NHID / 2);
        pack_kernel<<<(n + 255) / 256, 256>>>(b1, W2);
    }

    dim3 grid(NB / BM, NH);
    mhmlp_main_kernel<<<grid, NTHREADS, SMEM_DYN>>>(b2, out);
}

// round 12
// speedup vs baseline: 1.1661x; 1.0059x over previous
#include <cuda_runtime.h>
#include <cuda_fp16.h>
#include <cstdint>

// Problem dims
#define NB   2048
#define ND   512
#define NH   64
#define NHID 2048

// Tiling
#define BM   128
#define BN   256            // full n-tile; each warp-group owns a 128 half
#define BK   64
#define NTHREADS 256
#define NCHUNK 64           // 8 n-tiles * 8 k-tiles

// smem layout (bytes). A resident: 128 rows x 1024B, XOR swizzle = 131072.
// B: 2 groups x 3 stages x (64 k-rows x 256B) = 98304.
#define OFF_A  0
#define ASZ    131072
#define OFF_B  ASZ
#define BSTG_G 16384
#define GSTRIDE (3 * BSTG_G)                 // 49152 per group
#define NSTAGE 3
#define OFF_ROWACC (OFF_B + 2 * GSTRIDE)     // 229376
#define SMEM_DYN   (OFF_ROWACC + BM * 4)     // 229888

#define WSTRIDE ((size_t)BK * NHID * 2)      // 262144 B: k-chunk advance in g_Wh
#define WWRAP   ((long long)(BN * 2) - 7 * (long long)WSTRIDE)

// fp16 copies + packed epilogue params (device globals; allocation-free)
__device__ __half g_Wh[(size_t)NH * ND * NHID];   // [H][D][HID], n contiguous
__device__ __half g_Xh[(size_t)NB * ND];          // [B][D], k contiguous
__device__ float4 g_pk4[(size_t)NH * (NHID / 2)]; // (b1[2c],b1[2c+1],W2[2c],W2[2c+1])

__device__ __forceinline__ uint32_t smem_u32(const void* p) {
    return (uint32_t)__cvta_generic_to_shared(p);
}
__device__ __forceinline__ void cp16(uint32_t dst, const void* src) {
    asm volatile("cp.async.cg.shared.global [%0], [%1], 16;" :: "r"(dst), "l"(src));
}
__device__ __forceinline__ void cp_commit() {
    asm volatile("cp.async.commit_group;" ::: "memory");
}
__device__ __forceinline__ void gbar(int id) {
    asm volatile("bar.sync %0, 128;" :: "r"(id) : "memory");
}
__device__ __forceinline__ float lrelu(float v) {
    return (v >= 0.f) ? v : 0.01f * v;
}

// ---------------------------------------------------------------------------
// Converts
// ---------------------------------------------------------------------------
__global__ void convert_w_kernel(const float* __restrict__ W1) {
    size_t i = (size_t)blockIdx.x * blockDim.x + threadIdx.x;
    const size_t n4 = (size_t)NH * ND * NHID / 4;
    if (i >= n4) return;
    float4 v = ((const float4*)W1)[i];
    __half2* d = (__half2*)g_Wh;
    d[2 * i]     = __floats2half2_rn(v.x, v.y);
    d[2 * i + 1] = __floats2half2_rn(v.z, v.w);
}
__global__ void convert_x_kernel(const float* __restrict__ X) {
    size_t i = (size_t)blockIdx.x * blockDim.x + threadIdx.x;
    const size_t n4 = (size_t)NB * ND / 4;
    if (i >= n4) return;
    float4 v = ((const float4*)X)[i];
    __half2* d = (__half2*)g_Xh;
    d[2 * i]     = __floats2half2_rn(v.x, v.y);
    d[2 * i + 1] = __floats2half2_rn(v.z, v.w);
}
__global__ void pack_kernel(const float* __restrict__ b1, const float* __restrict__ W2) {
    int i = blockIdx.x * blockDim.x + threadIdx.x;     // 64 * 1024
    if (i >= NH * (NHID / 2)) return;
    int h = i >> 10, c = i & 1023;
    const float* b = b1 + (size_t)h * NHID + 2 * c;
    const float* w = W2 + (size_t)h * NHID + 2 * c;
    g_pk4[i] = make_float4(b[0], b[1], w[0], w[1]);
}

// ---------------------------------------------------------------------------
// Main fused kernel. CTA = (128-row m-tile, head). TWO independent warp
// groups of 4 share resident A but run private B pipelines + named barriers
// over opposite n-halves. A *and* B fragments register-double-buffered;
// A prefetch crosses the chunk boundary (A is resident -> no hazard).
// ---------------------------------------------------------------------------
__global__ void __launch_bounds__(NTHREADS, 1)
mhmlp_main_kernel(const float* __restrict__ b2, float* __restrict__ out)
{
    extern __shared__ char smem[];
    const uint32_t sbase = smem_u32(smem);
    float* rowacc = (float*)(smem + OFF_ROWACC);

    const int tid  = threadIdx.x;
    const int lane = tid & 31;
    const int wid  = tid >> 5;
    const int g    = wid >> 2;      // warp group 0/1 (n-half)
    const int w    = wid & 3;       // warp within group (SMSP index)
    const int wm   = w >> 1;        // 0..1 : 64-row band
    const int wn   = w & 1;         // 0..1 : 64-col band within 128-col half

    const int mt = blockIdx.x;      // 16 (fast dim -> head weights hot in L2)
    const int h  = blockIdx.y;      // 64
    const int m0 = mt * BM;

    if (tid < BM) rowacc[tid] = 0.f;

    const __half* __restrict__ Wh_h = g_Wh + (size_t)h * ND * NHID;
    const float4* __restrict__ pk_h = g_pk4 + (size_t)h * (NHID / 2);

    // ---- hoisted addressing ----
    const uint32_t xmask = ((uint32_t)(lane & 7)) << 4;
    uint32_t baseA[4];
    #pragma unroll
    for (int mi = 0; mi < 4; mi++) {
        int row = wm * 64 + mi * 16 + (lane & 15);
        baseA[mi] = sbase + OFF_A + (uint32_t)(row * 1024);
    }
    uint32_t laneOffA[4];
    #pragma unroll
    for (int ks = 0; ks < 4; ks++)
        laneOffA[ks] = ((uint32_t)(ks * 32 + (lane >> 4) * 16)) ^ xmask;
    uint32_t offBn[4];
    #pragma unroll
    for (int np = 0; np < 4; np++)
        offBn[np] = ((uint32_t)((wn * 64 + np * 16 + (lane >> 4) * 8) * 2)) ^ xmask;
    const uint32_t rowBbase = (uint32_t)((lane & 15) * 256);  // 256B rows

    // staging (per group: 128 threads stage 64 rows x 256B)
    const int t128 = tid & 127;
    const int r0 = t128 >> 4;            // 0..7
    const int sseg = t128 & 15;          // 0..15
    const uint32_t dstB0 = (uint32_t)(r0 * 256)
                         + (((uint32_t)(sseg * 16)) ^ (((uint32_t)r0) << 4));
    const char* pW = (const char*)Wh_h + (size_t)r0 * NHID * 2
                   + (size_t)sseg * 16 + (size_t)g * 128 * 2;
    const uint32_t gB = sbase + OFF_B + (uint32_t)g * GSTRIDE;

    // ---- prologue: stage ALL of A (all 256 threads), own commit group ----
    #pragma unroll
    for (int i = 0; i < 32; i++) {               // 8192 segs of 16B
        int t = tid + i * NTHREADS;
        int r = t >> 6, s = t & 63;
        const void* src = g_Xh + (size_t)(m0 + r) * ND + s * 8;
        uint32_t off = (uint32_t)(r * 1024 + s * 16);
        cp16(sbase + OFF_A + (off ^ (((uint32_t)(r & 7)) << 4)), src);
    }
    cp_commit();     // group [A]

    auto stageB = [&](int cc) {
        const uint32_t base = gB + (uint32_t)(cc % NSTAGE) * BSTG_G + dstB0;
        #pragma unroll
        for (int i = 0; i < 8; i++)              // rows r0 + 8i
            cp16(base + (uint32_t)(i * 2048), pW + (size_t)i * 8 * NHID * 2);
        cp_commit();
        pW += ((cc & 7) == 7) ? WWRAP : (long long)WSTRIDE;
    };

    stageB(0);       // group [B0]
    stageB(1);       // group [B1]
    asm volatile("cp.async.wait_group 2;" ::: "memory");   // A done
    __syncthreads();                                        // A visible to all

    float c[4][8][4];
    #pragma unroll
    for (int mi = 0; mi < 4; mi++)
        #pragma unroll
        for (int ni = 0; ni < 8; ni++)
            #pragma unroll
            for (int e = 0; e < 4; e++) c[mi][ni][e] = 0.f;
    float accrow[8] = {0.f,0.f,0.f,0.f,0.f,0.f,0.f,0.f};

    // A fragments double-buffered; preload (chunk 0, ks 0) — no hazard.
    uint32_t af[2][4][4];
    #pragma unroll
    for (int mi = 0; mi < 4; mi++) {
        uint32_t ad = baseA[mi] + laneOffA[0];
        asm volatile(
            "ldmatrix.sync.aligned.m8n8.x4.shared.b16 {%0,%1,%2,%3}, [%4];"
            : "=r"(af[0][mi][0]), "=r"(af[0][mi][1]),
              "=r"(af[0][mi][2]), "=r"(af[0][mi][3])
            : "r"(ad));
    }

    for (int cc = 0; cc < NCHUNK; ++cc) {
        asm volatile("cp.async.wait_group 1;" ::: "memory");
        gbar(1 + g);        // group-private barrier: chunk cc visible in-group

        if (cc + 2 < NCHUNK) stageB(cc + 2); else cp_commit();

        const uint32_t ktOff  = ((uint32_t)(cc & 7)) << 7;        // kt*128 B
        const uint32_t ktOffN = ((uint32_t)((cc + 1) & 7)) << 7;  // next chunk
        const uint32_t bB = gB + (uint32_t)(cc % NSTAGE) * BSTG_G + rowBbase;

        uint32_t bf[2][8][2];
        {   // preload B slice 0
            #pragma unroll
            for (int np = 0; np < 4; np++) {
                uint32_t ad = bB + offBn[np];
                uint32_t q0, q1, q2, q3;
                asm volatile(
                    "ldmatrix.sync.aligned.m8n8.x4.trans.shared.b16 {%0,%1,%2,%3}, [%4];"
                    : "=r"(q0), "=r"(q1), "=r"(q2), "=r"(q3) : "r"(ad));
                bf[0][2 * np][0] = q0;     bf[0][2 * np][1] = q1;
                bf[0][2 * np + 1][0] = q2; bf[0][2 * np + 1][1] = q3;
            }
        }

        #pragma unroll
        for (int ks = 0; ks < 4; ks++) {
            const int cur = ks & 1, nxt = cur ^ 1;
            // prefetch A for next slice (ks+1, or next chunk's ks0 — A is
            // resident, so the cross-chunk prefetch has no hazard)
            {
                uint32_t lo = (ks < 3) ? (laneOffA[ks + 1] + ktOff)
                                       : (laneOffA[0] + ktOffN);
                #pragma unroll
                for (int mi = 0; mi < 4; mi++) {
                    uint32_t ad = baseA[mi] + lo;
                    asm volatile(
                        "ldmatrix.sync.aligned.m8n8.x4.shared.b16 {%0,%1,%2,%3}, [%4];"
                        : "=r"(af[nxt][mi][0]), "=r"(af[nxt][mi][1]),
                          "=r"(af[nxt][mi][2]), "=r"(af[nxt][mi][3])
                        : "r"(ad));
                }
            }
            if (ks < 3) {     // prefetch B slice ks+1 under the MMA stream
                #pragma unroll
                for (int np = 0; np < 4; np++) {
                    uint32_t ad = bB + (uint32_t)((ks + 1) * 4096) + offBn[np];
                    uint32_t q0, q1, q2, q3;
                    asm volatile(
                        "ldmatrix.sync.aligned.m8n8.x4.trans.shared.b16 {%0,%1,%2,%3}, [%4];"
                        : "=r"(q0), "=r"(q1), "=r"(q2), "=r"(q3) : "r"(ad));
                    bf[nxt][2 * np][0] = q0;     bf[nxt][2 * np][1] = q1;
                    bf[nxt][2 * np + 1][0] = q2; bf[nxt][2 * np + 1][1] = q3;
                }
            }
            #pragma unroll
            for (int mi = 0; mi < 4; mi++)
                #pragma unroll
                for (int ni = 0; ni < 8; ni++) {
                    asm volatile(
                        "mma.sync.aligned.m16n8k16.row.col.f32.f16.f16.f32 "
                        "{%0,%1,%2,%3}, {%4,%5,%6,%7}, {%8,%9}, {%0,%1,%2,%3};"
                        : "+f"(c[mi][ni][0]), "+f"(c[mi][ni][1]),
                          "+f"(c[mi][ni][2]), "+f"(c[mi][ni][3])
                        : "r"(af[cur][mi][0]), "r"(af[cur][mi][1]),
                          "r"(af[cur][mi][2]), "r"(af[cur][mi][3]),
                          "r"(bf[cur][ni][0]), "r"(bf[cur][ni][1]));
                }
        }

        if ((cc & 7) == 7) {    // K complete -> fused epilogue for this n-tile
            const int nt = cc >> 3;
            #pragma unroll
            for (int ni = 0; ni < 8; ni++) {
                int cidx = nt * 128 + g * 64 + wn * 32 + ni * 4 + (lane & 3);
                float4 pk = __ldg(&pk_h[cidx]);
                #pragma unroll
                for (int mi = 0; mi < 4; mi++)
                    #pragma unroll
                    for (int e = 0; e < 4; e++) {
                        float bia = (e & 1) ? pk.y : pk.x;
                        float w2v = (e & 1) ? pk.w : pk.z;
                        float p = c[mi][ni][e] + bia;
                        accrow[mi * 2 + (e >> 1)] =
                            fmaf(lrelu(p), w2v, accrow[mi * 2 + (e >> 1)]);
                        c[mi][ni][e] = 0.f;
                    }
            }
        }
    }

    // reduce 4 lanes sharing each row, then across warps/groups via smem atomics
    #pragma unroll
    for (int off = 1; off <= 2; off <<= 1)
        #pragma unroll
        for (int j = 0; j < 8; j++)
            accrow[j] += __shfl_xor_sync(0xffffffffu, accrow[j], off);

    __syncthreads();   // rowacc zero-init visible; both groups done
    if ((lane & 3) == 0) {
        #pragma unroll
        for (int mi = 0; mi < 4; mi++)
            #pragma unroll
            for (int e2 = 0; e2 < 2; e2++) {
                int row = wm * 64 + mi * 16 + e2 * 8 + (lane >> 2);
                atomicAdd(&rowacc[row], accrow[mi * 2 + e2]);
            }
    }
    __syncthreads();
    if (tid < BM) {
        float v = rowacc[tid] + __ldg(&b2[h]);
        out[(size_t)(m0 + tid) * NH + h] = lrelu(v);
    }
}

// ---------------------------------------------------------------------------
extern "C" void kernel_launch(void* const* d_in, const int* in_sizes, int n_in,
                              void* d_out, int out_size) {
    const float* x  = (const float*)d_in[0];   // [2048, 512]
    const float* W1 = (const float*)d_in[1];   // [64, 512, 2048]
    const float* b1 = (const float*)d_in[2];   // [64, 2048]
    const float* W2 = (const float*)d_in[3];   // [64, 2048]
    const float* b2 = (const float*)d_in[4];   // [64]
    float* out = (float*)d_out;                // [2048, 64]
    (void)in_sizes; (void)n_in; (void)out_size;

    cudaFuncSetAttribute(mhmlp_main_kernel,
                         cudaFuncAttributeMaxDynamicSharedMemorySize, SMEM_DYN);

    {
        size_t n4 = (size_t)NH * ND * NHID / 4;
        convert_w_kernel<<<(int)((n4 + 255) / 256), 256>>>(W1);
    }
    {
        size_t n4 = (size_t)NB * ND / 4;
        convert_x_kernel<<<(int)((n4 + 255) / 256), 256>>>(x);
    }
    {
        int n = NH * (NHID / 2);
        pack_kernel<<<(n + 255) / 256, 256>>>(b1, W2);
    }

    dim3 grid(NB / BM, NH);
    mhmlp_main_kernel<<<grid, NTHREADS, SMEM_DYN>>>(b2, out);
}

// round 13
// speedup vs baseline: 1.1679x; 1.0016x over previous
#include <cuda_runtime.h>
#include <cuda_fp16.h>
#include <cstdint>

// Problem dims
#define NB   2048
#define ND   512
#define NH   64
#define NHID 2048

// Tiling
#define BM   128
#define BN   256            // full n-tile; 4 pipelets of 64 cols each
#define BK   64
#define NTHREADS 256
#define NCHUNK 64           // 8 n-tiles * 8 k-tiles

// smem layout (bytes). A resident: 128 rows x 1024B, XOR swizzle = 131072.
// B: 4 pipelets x 3 stages x (64 k-rows x 128B) = 98304.
#define OFF_A  0
#define ASZ    131072
#define OFF_B  ASZ
#define BSTG_P 8192
#define PSTRIDE (3 * BSTG_P)                 // 24576 per pipelet
#define NSTAGE 3
#define OFF_ROWACC (OFF_B + 4 * PSTRIDE)     // 229376
#define SMEM_DYN   (OFF_ROWACC + BM * 4)     // 229888

#define WSTRIDE ((size_t)BK * NHID * 2)      // 262144 B: k-chunk advance in g_Wh
#define WWRAP   ((long long)(BN * 2) - 7 * (long long)WSTRIDE)

// fp16 copies + packed epilogue params (device globals; allocation-free)
__device__ __half g_Wh[(size_t)NH * ND * NHID];   // [H][D][HID], n contiguous
__device__ __half g_Xh[(size_t)NB * ND];          // [B][D], k contiguous
__device__ float4 g_pk4[(size_t)NH * (NHID / 2)]; // (b1[2c],b1[2c+1],W2[2c],W2[2c+1])

__device__ __forceinline__ uint32_t smem_u32(const void* p) {
    return (uint32_t)__cvta_generic_to_shared(p);
}
__device__ __forceinline__ void cp16(uint32_t dst, const void* src) {
    asm volatile("cp.async.cg.shared.global [%0], [%1], 16;" :: "r"(dst), "l"(src));
}
__device__ __forceinline__ void cp_commit() {
    asm volatile("cp.async.commit_group;" ::: "memory");
}
__device__ __forceinline__ void pbar(int id) {
    asm volatile("bar.sync %0, 64;" :: "r"(id) : "memory");
}
__device__ __forceinline__ float lrelu(float v) {
    return (v >= 0.f) ? v : 0.01f * v;
}

// ---------------------------------------------------------------------------
// Converts
// ---------------------------------------------------------------------------
__global__ void convert_w_kernel(const float* __restrict__ W1) {
    size_t i = (size_t)blockIdx.x * blockDim.x + threadIdx.x;
    const size_t n4 = (size_t)NH * ND * NHID / 4;
    if (i >= n4) return;
    float4 v = ((const float4*)W1)[i];
    __half2* d = (__half2*)g_Wh;
    d[2 * i]     = __floats2half2_rn(v.x, v.y);
    d[2 * i + 1] = __floats2half2_rn(v.z, v.w);
}
__global__ void convert_x_kernel(const float* __restrict__ X) {
    size_t i = (size_t)blockIdx.x * blockDim.x + threadIdx.x;
    const size_t n4 = (size_t)NB * ND / 4;
    if (i >= n4) return;
    float4 v = ((const float4*)X)[i];
    __half2* d = (__half2*)g_Xh;
    d[2 * i]     = __floats2half2_rn(v.x, v.y);
    d[2 * i + 1] = __floats2half2_rn(v.z, v.w);
}
__global__ void pack_kernel(const float* __restrict__ b1, const float* __restrict__ W2) {
    int i = blockIdx.x * blockDim.x + threadIdx.x;     // 64 * 1024
    if (i >= NH * (NHID / 2)) return;
    int h = i >> 10, c = i & 1023;
    const float* b = b1 + (size_t)h * NHID + 2 * c;
    const float* w = W2 + (size_t)h * NHID + 2 * c;
    g_pk4[i] = make_float4(b[0], b[1], w[0], w[1]);
}

// ---------------------------------------------------------------------------
// Main fused kernel. CTA = (128-row m-tile, head). FOUR independent pipelets
// (2 warps each) share resident A; each owns a private 64-col B stream,
// private cp.async groups, and a private 64-thread named barrier. Four
// independently-drifting schedules keep the tensor pipe covered through
// any one pipelet's barrier/staging/epilogue window.
// ---------------------------------------------------------------------------
__global__ void __launch_bounds__(NTHREADS, 1)
mhmlp_main_kernel(const float* __restrict__ b2, float* __restrict__ out)
{
    extern __shared__ char smem[];
    const uint32_t sbase = smem_u32(smem);
    float* rowacc = (float*)(smem + OFF_ROWACC);

    const int tid  = threadIdx.x;
    const int lane = tid & 31;
    const int wid  = tid >> 5;
    const int g    = wid >> 2;      // n-half 0/1
    const int w    = wid & 3;
    const int wm   = w >> 1;        // 0..1 : 64-row band
    const int wn   = w & 1;         // 0..1 : 64-col band within half
    const int p    = g * 2 + wn;    // pipelet 0..3
    const int noff = g * 128 + wn * 64;   // pipelet's n-offset in the 256 tile

    const int mt = blockIdx.x;      // 16 (fast dim -> head weights hot in L2)
    const int h  = blockIdx.y;      // 64
    const int m0 = mt * BM;

    if (tid < BM) rowacc[tid] = 0.f;

    const __half* __restrict__ Wh_h = g_Wh + (size_t)h * ND * NHID;
    const float4* __restrict__ pk_h = g_pk4 + (size_t)h * (NHID / 2);

    // ---- hoisted addressing ----
    const uint32_t xmask = ((uint32_t)(lane & 7)) << 4;
    uint32_t baseA[4];
    #pragma unroll
    for (int mi = 0; mi < 4; mi++) {
        int row = wm * 64 + mi * 16 + (lane & 15);
        baseA[mi] = sbase + OFF_A + (uint32_t)(row * 1024);
    }
    uint32_t laneOffA[4];
    #pragma unroll
    for (int ks = 0; ks < 4; ks++)
        laneOffA[ks] = ((uint32_t)(ks * 32 + (lane >> 4) * 16)) ^ xmask;
    // B: 128B rows; col byte = np*32 + (lane>>4)*16; row = lane&15
    uint32_t offBn[4];
    #pragma unroll
    for (int np = 0; np < 4; np++)
        offBn[np] = ((uint32_t)(np * 32 + (lane >> 4) * 16)) ^ xmask;
    const uint32_t rowBbase = (uint32_t)((lane & 15) * 128);

    // staging: pipelet's 64 threads stage 64 rows x 128B
    const int t64 = wm * 32 + lane;       // 0..63 within pipelet
    const int r0 = t64 >> 3;              // 0..7
    const int seg = t64 & 7;              // 0..7
    const uint32_t dstB0 = ((uint32_t)(r0 * 128 + seg * 16)) ^ (((uint32_t)r0) << 4);
    const char* pW = (const char*)Wh_h + (size_t)r0 * NHID * 2
                   + (size_t)noff * 2 + (size_t)seg * 16;
    const uint32_t pB = sbase + OFF_B + (uint32_t)p * PSTRIDE;

    // ---- prologue: stage ALL of A (all 256 threads), own commit group ----
    #pragma unroll
    for (int i = 0; i < 32; i++) {               // 8192 segs of 16B
        int t = tid + i * NTHREADS;
        int r = t >> 6, s = t & 63;
        const void* src = g_Xh + (size_t)(m0 + r) * ND + s * 8;
        uint32_t off = (uint32_t)(r * 1024 + s * 16);
        cp16(sbase + OFF_A + (off ^ (((uint32_t)(r & 7)) << 4)), src);
    }
    cp_commit();     // group [A]

    auto stageB = [&](int cc) {
        const uint32_t base = pB + (uint32_t)(cc % NSTAGE) * BSTG_P + dstB0;
        #pragma unroll
        for (int i = 0; i < 8; i++)              // rows r0 + 8i
            cp16(base + (uint32_t)(i * 1024), pW + (size_t)i * 8 * NHID * 2);
        cp_commit();
        pW += ((cc & 7) == 7) ? WWRAP : (long long)WSTRIDE;
    };

    stageB(0);       // group [B0]
    stageB(1);       // group [B1]
    asm volatile("cp.async.wait_group 2;" ::: "memory");   // A done
    __syncthreads();                                        // A visible to all

    float c[4][8][4];
    #pragma unroll
    for (int mi = 0; mi < 4; mi++)
        #pragma unroll
        for (int ni = 0; ni < 8; ni++)
            #pragma unroll
            for (int e = 0; e < 4; e++) c[mi][ni][e] = 0.f;
    float accrow[8] = {0.f,0.f,0.f,0.f,0.f,0.f,0.f,0.f};

    for (int cc = 0; cc < NCHUNK; ++cc) {
        asm volatile("cp.async.wait_group 1;" ::: "memory");
        pbar(1 + p);        // pipelet barrier: chunk cc visible to both warps

        if (cc + 2 < NCHUNK) stageB(cc + 2); else cp_commit();

        const uint32_t ktOff = ((uint32_t)(cc & 7)) << 7;   // kt*128 bytes
        const uint32_t bB = pB + (uint32_t)(cc % NSTAGE) * BSTG_P + rowBbase;

        uint32_t bf[2][8][2];
        {   // preload B slice 0
            #pragma unroll
            for (int np = 0; np < 4; np++) {
                uint32_t ad = bB + offBn[np];
                uint32_t q0, q1, q2, q3;
                asm volatile(
                    "ldmatrix.sync.aligned.m8n8.x4.trans.shared.b16 {%0,%1,%2,%3}, [%4];"
                    : "=r"(q0), "=r"(q1), "=r"(q2), "=r"(q3) : "r"(ad));
                bf[0][2 * np][0] = q0;     bf[0][2 * np][1] = q1;
                bf[0][2 * np + 1][0] = q2; bf[0][2 * np + 1][1] = q3;
            }
        }

        #pragma unroll
        for (int ks = 0; ks < 4; ks++) {
            const int cur = ks & 1, nxt = cur ^ 1;
            uint32_t a[4][4];
            #pragma unroll
            for (int mi = 0; mi < 4; mi++) {
                uint32_t ad = baseA[mi] + laneOffA[ks] + ktOff;
                asm volatile(
                    "ldmatrix.sync.aligned.m8n8.x4.shared.b16 {%0,%1,%2,%3}, [%4];"
                    : "=r"(a[mi][0]), "=r"(a[mi][1]), "=r"(a[mi][2]), "=r"(a[mi][3])
                    : "r"(ad));
            }
            if (ks < 3) {     // prefetch B slice ks+1 under the MMA stream
                #pragma unroll
                for (int np = 0; np < 4; np++) {
                    uint32_t ad = bB + (uint32_t)((ks + 1) * 2048) + offBn[np];
                    uint32_t q0, q1, q2, q3;
                    asm volatile(
                        "ldmatrix.sync.aligned.m8n8.x4.trans.shared.b16 {%0,%1,%2,%3}, [%4];"
                        : "=r"(q0), "=r"(q1), "=r"(q2), "=r"(q3) : "r"(ad));
                    bf[nxt][2 * np][0] = q0;     bf[nxt][2 * np][1] = q1;
                    bf[nxt][2 * np + 1][0] = q2; bf[nxt][2 * np + 1][1] = q3;
                }
            }
            #pragma unroll
            for (int mi = 0; mi < 4; mi++)
                #pragma unroll
                for (int ni = 0; ni < 8; ni++) {
                    asm volatile(
                        "mma.sync.aligned.m16n8k16.row.col.f32.f16.f16.f32 "
                        "{%0,%1,%2,%3}, {%4,%5,%6,%7}, {%8,%9}, {%0,%1,%2,%3};"
                        : "+f"(c[mi][ni][0]), "+f"(c[mi][ni][1]),
                          "+f"(c[mi][ni][2]), "+f"(c[mi][ni][3])
                        : "r"(a[mi][0]), "r"(a[mi][1]), "r"(a[mi][2]), "r"(a[mi][3]),
                          "r"(bf[cur][ni][0]), "r"(bf[cur][ni][1]));
                }
        }

        if ((cc & 7) == 7) {    // K complete -> fused epilogue for this n-tile
            const int nt = cc >> 3;
            #pragma unroll
            for (int ni = 0; ni < 8; ni++) {
                int cidx = nt * 128 + g * 64 + wn * 32 + ni * 4 + (lane & 3);
                float4 pk = __ldg(&pk_h[cidx]);
                #pragma unroll
                for (int mi = 0; mi < 4; mi++)
                    #pragma unroll
                    for (int e = 0; e < 4; e++) {
                        float bia = (e & 1) ? pk.y : pk.x;
                        float w2v = (e & 1) ? pk.w : pk.z;
                        float q = c[mi][ni][e] + bia;
                        accrow[mi * 2 + (e >> 1)] =
                            fmaf(lrelu(q), w2v, accrow[mi * 2 + (e >> 1)]);
                        c[mi][ni][e] = 0.f;
                    }
            }
        }
    }

    // reduce 4 lanes sharing each row, then across warps via smem atomics
    #pragma unroll
    for (int off = 1; off <= 2; off <<= 1)
        #pragma unroll
        for (int j = 0; j < 8; j++)
            accrow[j] += __shfl_xor_sync(0xffffffffu, accrow[j], off);

    __syncthreads();   // rowacc zero-init visible; all pipelets done
    if ((lane & 3) == 0) {
        #pragma unroll
        for (int mi = 0; mi < 4; mi++)
            #pragma unroll
            for (int e2 = 0; e2 < 2; e2++) {
                int row = wm * 64 + mi * 16 + e2 * 8 + (lane >> 2);
                atomicAdd(&rowacc[row], accrow[mi * 2 + e2]);
            }
    }
    __syncthreads();
    if (tid < BM) {
        float v = rowacc[tid] + __ldg(&b2[h]);
        out[(size_t)(m0 + tid) * NH + h] = lrelu(v);
    }
}

// ---------------------------------------------------------------------------
extern "C" void kernel_launch(void* const* d_in, const int* in_sizes, int n_in,
                              void* d_out, int out_size) {
    const float* x  = (const float*)d_in[0];   // [2048, 512]
    const float* W1 = (const float*)d_in[1];   // [64, 512, 2048]
    const float* b1 = (const float*)d_in[2];   // [64, 2048]
    const float* W2 = (const float*)d_in[3];   // [64, 2048]
    const float* b2 = (const float*)d_in[4];   // [64]
    float* out = (float*)d_out;                // [2048, 64]
    (void)in_sizes; (void)n_in; (void)out_size;

    cudaFuncSetAttribute(mhmlp_main_kernel,
                         cudaFuncAttributeMaxDynamicSharedMemorySize, SMEM_DYN);

    {
        size_t n4 = (size_t)NH * ND * NHID / 4;
        convert_w_kernel<<<(int)((n4 + 255) / 256), 256>>>(W1);
    }
    {
        size_t n4 = (size_t)NB * ND / 4;
        convert_x_kernel<<<(int)((n4 + 255) / 256), 256>>>(x);
    }
    {
        int n = NH * (NHID / 2);
        pack_kernel<<<(n + 255) / 256, 256>>>(b1, W2);
    }

    dim3 grid(NB / BM, NH);
    mhmlp_main_kernel<<<grid, NTHREADS, SMEM_DYN>>>(b2, out);
}

// round 14
// speedup vs baseline: 1.1851x; 1.0147x over previous
#include <cuda_runtime.h>
#include <cuda_fp16.h>
#include <cstdint>

// Problem dims
#define NB   2048
#define ND   512
#define NH   64
#define NHID 2048

// Tiling
#define BM   128
#define BN   256            // full n-tile; 4 pipelets of 64 cols each
#define BK   64
#define NTHREADS 256
#define NCHUNK 64           // 8 n-tiles * 8 k-tiles

// smem layout (bytes). A resident: 128 rows x 1024B, XOR swizzle = 131072.
// B: 4 pipelets x 3 stages x (64 k-rows x 128B) = 98304.
#define OFF_A  0
#define ASZ    131072
#define OFF_B  ASZ
#define BSTG_P 8192
#define PSTRIDE (3 * BSTG_P)                 // 24576 per pipelet
#define NSTAGE 3
#define OFF_ROWACC (OFF_B + 4 * PSTRIDE)     // 229376
#define SMEM_DYN   (OFF_ROWACC + BM * 4)     // 229888

#define WSTRIDE ((size_t)BK * NHID * 2)      // 262144 B: k-chunk advance in g_Wh
#define WWRAP   ((long long)(BN * 2) - 7 * (long long)WSTRIDE)

// fp16 copies + packed epilogue params (device globals; allocation-free)
__device__ __half g_Wh[(size_t)NH * ND * NHID];   // [H][D][HID], n contiguous
__device__ __half g_Xh[(size_t)NB * ND];          // [B][D], k contiguous
__device__ float4 g_pk4[(size_t)NH * (NHID / 2)]; // (b1[2c],b1[2c+1],W2[2c],W2[2c+1])

__device__ __forceinline__ uint32_t smem_u32(const void* p) {
    return (uint32_t)__cvta_generic_to_shared(p);
}
__device__ __forceinline__ void cp16(uint32_t dst, const void* src) {
    asm volatile("cp.async.cg.shared.global [%0], [%1], 16;" :: "r"(dst), "l"(src));
}
__device__ __forceinline__ void cp_commit() {
    asm volatile("cp.async.commit_group;" ::: "memory");
}
__device__ __forceinline__ void pbar(int id) {
    asm volatile("bar.sync %0, 64;" :: "r"(id) : "memory");
}
__device__ __forceinline__ float lrelu(float v) {
    return (v >= 0.f) ? v : 0.01f * v;
}

// ---------------------------------------------------------------------------
// Converts
// ---------------------------------------------------------------------------
__global__ void convert_w_kernel(const float* __restrict__ W1) {
    size_t i = (size_t)blockIdx.x * blockDim.x + threadIdx.x;
    const size_t n4 = (size_t)NH * ND * NHID / 4;
    if (i >= n4) return;
    float4 v = ((const float4*)W1)[i];
    __half2* d = (__half2*)g_Wh;
    d[2 * i]     = __floats2half2_rn(v.x, v.y);
    d[2 * i + 1] = __floats2half2_rn(v.z, v.w);
}
__global__ void convert_x_kernel(const float* __restrict__ X) {
    size_t i = (size_t)blockIdx.x * blockDim.x + threadIdx.x;
    const size_t n4 = (size_t)NB * ND / 4;
    if (i >= n4) return;
    float4 v = ((const float4*)X)[i];
    __half2* d = (__half2*)g_Xh;
    d[2 * i]     = __floats2half2_rn(v.x, v.y);
    d[2 * i + 1] = __floats2half2_rn(v.z, v.w);
}
__global__ void pack_kernel(const float* __restrict__ b1, const float* __restrict__ W2) {
    int i = blockIdx.x * blockDim.x + threadIdx.x;     // 64 * 1024
    if (i >= NH * (NHID / 2)) return;
    int h = i >> 10, c = i & 1023;
    const float* b = b1 + (size_t)h * NHID + 2 * c;
    const float* w = W2 + (size_t)h * NHID + 2 * c;
    g_pk4[i] = make_float4(b[0], b[1], w[0], w[1]);
}

// ---------------------------------------------------------------------------
// Main fused kernel. CTA = (128-row m-tile, head). FOUR independent pipelets
// (2 warps each) share resident A; each owns a private 64-col B stream,
// private cp.async groups, and a private 64-thread named barrier.
// NEW: pipelet p starts with a ~quarter-chunk * p spin so the four schedules
// run phase-shifted for the whole kernel -> at most one pipelet is in a
// barrier/staging/epilogue drain at any instant, others cover the tensor pipe.
// ---------------------------------------------------------------------------
__global__ void __launch_bounds__(NTHREADS, 1)
mhmlp_main_kernel(const float* __restrict__ b2, float* __restrict__ out)
{
    extern __shared__ char smem[];
    const uint32_t sbase = smem_u32(smem);
    float* rowacc = (float*)(smem + OFF_ROWACC);

    const int tid  = threadIdx.x;
    const int lane = tid & 31;
    const int wid  = tid >> 5;
    const int g    = wid >> 2;      // n-half 0/1
    const int w    = wid & 3;
    const int wm   = w >> 1;        // 0..1 : 64-row band
    const int wn   = w & 1;         // 0..1 : 64-col band within half
    const int p    = g * 2 + wn;    // pipelet 0..3
    const int noff = g * 128 + wn * 64;   // pipelet's n-offset in the 256 tile

    const int mt = blockIdx.x;      // 16 (fast dim -> head weights hot in L2)
    const int h  = blockIdx.y;      // 64
    const int m0 = mt * BM;

    if (tid < BM) rowacc[tid] = 0.f;

    const __half* __restrict__ Wh_h = g_Wh + (size_t)h * ND * NHID;
    const float4* __restrict__ pk_h = g_pk4 + (size_t)h * (NHID / 2);

    // ---- hoisted addressing ----
    const uint32_t xmask = ((uint32_t)(lane & 7)) << 4;
    uint32_t baseA[4];
    #pragma unroll
    for (int mi = 0; mi < 4; mi++) {
        int row = wm * 64 + mi * 16 + (lane & 15);
        baseA[mi] = sbase + OFF_A + (uint32_t)(row * 1024);
    }
    uint32_t laneOffA[4];
    #pragma unroll
    for (int ks = 0; ks < 4; ks++)
        laneOffA[ks] = ((uint32_t)(ks * 32 + (lane >> 4) * 16)) ^ xmask;
    // B: 128B rows; col byte = np*32 + (lane>>4)*16; row = lane&15
    uint32_t offBn[4];
    #pragma unroll
    for (int np = 0; np < 4; np++)
        offBn[np] = ((uint32_t)(np * 32 + (lane >> 4) * 16)) ^ xmask;
    const uint32_t rowBbase = (uint32_t)((lane & 15) * 128);

    // staging: pipelet's 64 threads stage 64 rows x 128B
    const int t64 = wm * 32 + lane;       // 0..63 within pipelet
    const int r0 = t64 >> 3;              // 0..7
    const int seg = t64 & 7;              // 0..7
    const uint32_t dstB0 = ((uint32_t)(r0 * 128 + seg * 16)) ^ (((uint32_t)r0) << 4);
    const char* pW = (const char*)Wh_h + (size_t)r0 * NHID * 2
                   + (size_t)noff * 2 + (size_t)seg * 16;
    const uint32_t pB = sbase + OFF_B + (uint32_t)p * PSTRIDE;

    // ---- prologue: stage ALL of A (all 256 threads), own commit group ----
    #pragma unroll
    for (int i = 0; i < 32; i++) {               // 8192 segs of 16B
        int t = tid + i * NTHREADS;
        int r = t >> 6, s = t & 63;
        const void* src = g_Xh + (size_t)(m0 + r) * ND + s * 8;
        uint32_t off = (uint32_t)(r * 1024 + s * 16);
        cp16(sbase + OFF_A + (off ^ (((uint32_t)(r & 7)) << 4)), src);
    }
    cp_commit();     // group [A]

    auto stageB = [&](int cc) {
        const uint32_t base = pB + (uint32_t)(cc % NSTAGE) * BSTG_P + dstB0;
        #pragma unroll
        for (int i = 0; i < 8; i++)              // rows r0 + 8i
            cp16(base + (uint32_t)(i * 1024), pW + (size_t)i * 8 * NHID * 2);
        cp_commit();
        pW += ((cc & 7) == 7) ? WWRAP : (long long)WSTRIDE;
    };

    stageB(0);       // group [B0]
    stageB(1);       // group [B1]
    asm volatile("cp.async.wait_group 2;" ::: "memory");   // A done
    __syncthreads();                                        // A visible to all

    // ---- phase skew: pipelet p delays ~quarter-chunk * p (dep-chain FFMA,
    // ~4 cyc/iter). One-time cost <=2100 cyc; desynchronizes all per-chunk
    // drain windows across pipelets for the rest of the kernel.
    {
        float dummy = (float)(tid + 1);
        const int iters = p * 172;
        for (int i = 0; i < iters; i++)
            dummy = fmaf(dummy, 0.99999988f, 1.0e-7f);
        if (dummy == 1.2345678e-33f) rowacc[tid & (BM - 1)] = dummy;  // opaque
    }

    float c[4][8][4];
    #pragma unroll
    for (int mi = 0; mi < 4; mi++)
        #pragma unroll
        for (int ni = 0; ni < 8; ni++)
            #pragma unroll
            for (int e = 0; e < 4; e++) c[mi][ni][e] = 0.f;
    float accrow[8] = {0.f,0.f,0.f,0.f,0.f,0.f,0.f,0.f};

    for (int cc = 0; cc < NCHUNK; ++cc) {
        asm volatile("cp.async.wait_group 1;" ::: "memory");
        pbar(1 + p);        // pipelet barrier: chunk cc visible to both warps

        if (cc + 2 < NCHUNK) stageB(cc + 2); else cp_commit();

        const uint32_t ktOff = ((uint32_t)(cc & 7)) << 7;   // kt*128 bytes
        const uint32_t bB = pB + (uint32_t)(cc % NSTAGE) * BSTG_P + rowBbase;

        uint32_t bf[2][8][2];
        {   // preload B slice 0
            #pragma unroll
            for (int np = 0; np < 4; np++) {
                uint32_t ad = bB + offBn[np];
                uint32_t q0, q1, q2, q3;
                asm volatile(
                    "ldmatrix.sync.aligned.m8n8.x4.trans.shared.b16 {%0,%1,%2,%3}, [%4];"
                    : "=r"(q0), "=r"(q1), "=r"(q2), "=r"(q3) : "r"(ad));
                bf[0][2 * np][0] = q0;     bf[0][2 * np][1] = q1;
                bf[0][2 * np + 1][0] = q2; bf[0][2 * np + 1][1] = q3;
            }
        }

        #pragma unroll
        for (int ks = 0; ks < 4; ks++) {
            const int cur = ks & 1, nxt = cur ^ 1;
            uint32_t a[4][4];
            #pragma unroll
            for (int mi = 0; mi < 4; mi++) {
                uint32_t ad = baseA[mi] + laneOffA[ks] + ktOff;
                asm volatile(
                    "ldmatrix.sync.aligned.m8n8.x4.shared.b16 {%0,%1,%2,%3}, [%4];"
                    : "=r"(a[mi][0]), "=r"(a[mi][1]), "=r"(a[mi][2]), "=r"(a[mi][3])
                    : "r"(ad));
            }
            if (ks < 3) {     // prefetch B slice ks+1 under the MMA stream
                #pragma unroll
                for (int np = 0; np < 4; np++) {
                    uint32_t ad = bB + (uint32_t)((ks + 1) * 2048) + offBn[np];
                    uint32_t q0, q1, q2, q3;
                    asm volatile(
                        "ldmatrix.sync.aligned.m8n8.x4.trans.shared.b16 {%0,%1,%2,%3}, [%4];"
                        : "=r"(q0), "=r"(q1), "=r"(q2), "=r"(q3) : "r"(ad));
                    bf[nxt][2 * np][0] = q0;     bf[nxt][2 * np][1] = q1;
                    bf[nxt][2 * np + 1][0] = q2; bf[nxt][2 * np + 1][1] = q3;
                }
            }
            #pragma unroll
            for (int mi = 0; mi < 4; mi++)
                #pragma unroll
                for (int ni = 0; ni < 8; ni++) {
                    asm volatile(
                        "mma.sync.aligned.m16n8k16.row.col.f32.f16.f16.f32 "
                        "{%0,%1,%2,%3}, {%4,%5,%6,%7}, {%8,%9}, {%0,%1,%2,%3};"
                        : "+f"(c[mi][ni][0]), "+f"(c[mi][ni][1]),
                          "+f"(c[mi][ni][2]), "+f"(c[mi][ni][3])
                        : "r"(a[mi][0]), "r"(a[mi][1]), "r"(a[mi][2]), "r"(a[mi][3]),
                          "r"(bf[cur][ni][0]), "r"(bf[cur][ni][1]));
                }
        }

        if ((cc & 7) == 7) {    // K complete -> fused epilogue for this n-tile
            const int nt = cc >> 3;
            #pragma unroll
            for (int ni = 0; ni < 8; ni++) {
                int cidx = nt * 128 + g * 64 + wn * 32 + ni * 4 + (lane & 3);
                float4 pk = __ldg(&pk_h[cidx]);
                #pragma unroll
                for (int mi = 0; mi < 4; mi++)
                    #pragma unroll
                    for (int e = 0; e < 4; e++) {
                        float bia = (e & 1) ? pk.y : pk.x;
                        float w2v = (e & 1) ? pk.w : pk.z;
                        float q = c[mi][ni][e] + bia;
                        accrow[mi * 2 + (e >> 1)] =
                            fmaf(lrelu(q), w2v, accrow[mi * 2 + (e >> 1)]);
                        c[mi][ni][e] = 0.f;
                    }
            }
        }
    }

    // reduce 4 lanes sharing each row, then across warps via smem atomics
    #pragma unroll
    for (int off = 1; off <= 2; off <<= 1)
        #pragma unroll
        for (int j = 0; j < 8; j++)
            accrow[j] += __shfl_xor_sync(0xffffffffu, accrow[j], off);

    __syncthreads();   // rowacc zero-init visible; all pipelets done
    if ((lane & 3) == 0) {
        #pragma unroll
        for (int mi = 0; mi < 4; mi++)
            #pragma unroll
            for (int e2 = 0; e2 < 2; e2++) {
                int row = wm * 64 + mi * 16 + e2 * 8 + (lane >> 2);
                atomicAdd(&rowacc[row], accrow[mi * 2 + e2]);
            }
    }
    __syncthreads();
    if (tid < BM) {
        float v = rowacc[tid] + __ldg(&b2[h]);
        out[(size_t)(m0 + tid) * NH + h] = lrelu(v);
    }
}

// ---------------------------------------------------------------------------
extern "C" void kernel_launch(void* const* d_in, const int* in_sizes, int n_in,
                              void* d_out, int out_size) {
    const float* x  = (const float*)d_in[0];   // [2048, 512]
    const float* W1 = (const float*)d_in[1];   // [64, 512, 2048]
    const float* b1 = (const float*)d_in[2];   // [64, 2048]
    const float* W2 = (const float*)d_in[3];   // [64, 2048]
    const float* b2 = (const float*)d_in[4];   // [64]
    float* out = (float*)d_out;                // [2048, 64]
    (void)in_sizes; (void)n_in; (void)out_size;

    cudaFuncSetAttribute(mhmlp_main_kernel,
                         cudaFuncAttributeMaxDynamicSharedMemorySize, SMEM_DYN);

    {
        size_t n4 = (size_t)NH * ND * NHID / 4;
        convert_w_kernel<<<(int)((n4 + 255) / 256), 256>>>(W1);
    }
    {
        size_t n4 = (size_t)NB * ND / 4;
        convert_x_kernel<<<(int)((n4 + 255) / 256), 256>>>(x);
    }
    {
        int n = NH * (NHID / 2);
        pack_kernel<<<(n + 255) / 256, 256>>>(b1, W2);
    }

    dim3 grid(NB / BM, NH);
    mhmlp_main_kernel<<<grid, NTHREADS, SMEM_DYN>>>(b2, out);
}

// round 15
// speedup vs baseline: 1.2052x; 1.0170x over previous
#include <cuda_runtime.h>
#include <cuda_fp16.h>
#include <cstdint>

// Problem dims
#define NB   2048
#define ND   512
#define NH   64
#define NHID 2048

// Tiling
#define BM   128
#define BN   256            // full n-tile; 4 pipelets of 64 cols each
#define BK   64
#define NTHREADS 256
#define NCHUNK 64           // 8 n-tiles * 8 k-tiles

// smem layout (bytes). A resident: 128 rows x 1024B, XOR swizzle = 131072.
// B: 4 pipelets x 3 stages x (64 k-rows x 128B) = 98304.
#define OFF_A  0
#define ASZ    131072
#define OFF_B  ASZ
#define BSTG_P 8192
#define PSTRIDE (3 * BSTG_P)                 // 24576 per pipelet
#define NSTAGE 3
#define OFF_ROWACC (OFF_B + 4 * PSTRIDE)     // 229376
#define SMEM_DYN   (OFF_ROWACC + BM * 4)     // 229888

#define WSTRIDE ((size_t)BK * NHID * 2)      // 262144 B: k-chunk advance in g_Wh
#define WWRAP   ((long long)(BN * 2) - 7 * (long long)WSTRIDE)

// fused convert kernel block partition
#define WBLKS  32768        // W: 2 float4 per thread
#define XBLKS  1024
#define PBLKS  256

// fp16 copies + packed epilogue params (device globals; allocation-free)
__device__ __half g_Wh[(size_t)NH * ND * NHID];   // [H][D][HID], n contiguous
__device__ __half g_Xh[(size_t)NB * ND];          // [B][D], k contiguous
__device__ float4 g_pk4[(size_t)NH * (NHID / 2)]; // (b1[2c],b1[2c+1],W2[2c],W2[2c+1])

__device__ __forceinline__ uint32_t smem_u32(const void* p) {
    return (uint32_t)__cvta_generic_to_shared(p);
}
__device__ __forceinline__ void cp16(uint32_t dst, const void* src) {
    asm volatile("cp.async.cg.shared.global [%0], [%1], 16;" :: "r"(dst), "l"(src));
}
__device__ __forceinline__ void cp_commit() {
    asm volatile("cp.async.commit_group;" ::: "memory");
}
__device__ __forceinline__ void pbar(int id) {
    asm volatile("bar.sync %0, 64;" :: "r"(id) : "memory");
}
__device__ __forceinline__ float lrelu(float v) {
    return (v >= 0.f) ? v : 0.01f * v;
}

// ---------------------------------------------------------------------------
// Fused prep kernel: W convert (MLP=2), X convert, b1/W2 pack — one launch.
// Small X/pack blocks overlap with the DRAM-bound W portion.
// ---------------------------------------------------------------------------
__global__ void convert_all_kernel(const float* __restrict__ W1,
                                   const float* __restrict__ X,
                                   const float* __restrict__ b1,
                                   const float* __restrict__ W2)
{
    const int b = blockIdx.x;
    const int tid = threadIdx.x;

    if (b < WBLKS) {
        // W: each thread converts 2 adjacent float4 (32B read, 16B write)
        size_t u = ((size_t)b * 256 + tid) * 2;       // float4 unit index
        const float4* src = (const float4*)W1;
        __half2* d = (__half2*)g_Wh;
        float4 v0 = src[u], v1 = src[u + 1];
        d[2 * u]     = __floats2half2_rn(v0.x, v0.y);
        d[2 * u + 1] = __floats2half2_rn(v0.z, v0.w);
        d[2 * u + 2] = __floats2half2_rn(v1.x, v1.y);
        d[2 * u + 3] = __floats2half2_rn(v1.z, v1.w);
    } else if (b < WBLKS + XBLKS) {
        size_t i = (size_t)(b - WBLKS) * 256 + tid;   // float4 unit
        float4 v = ((const float4*)X)[i];
        __half2* d = (__half2*)g_Xh;
        d[2 * i]     = __floats2half2_rn(v.x, v.y);
        d[2 * i + 1] = __floats2half2_rn(v.z, v.w);
    } else {
        int i = (b - WBLKS - XBLKS) * 256 + tid;      // 0 .. 65535
        int h = i >> 10, c = i & 1023;
        const float* bb = b1 + (size_t)h * NHID + 2 * c;
        const float* ww = W2 + (size_t)h * NHID + 2 * c;
        g_pk4[i] = make_float4(bb[0], bb[1], ww[0], ww[1]);
    }
}

// ---------------------------------------------------------------------------
// Main fused kernel (unchanged from R14). CTA = (128-row m-tile, head).
// FOUR independent pipelets (2 warps each) share resident A; private 64-col
// B streams, private cp.async groups, private 64-thread named barriers,
// quarter-chunk phase skew between pipelets.
// ---------------------------------------------------------------------------
__global__ void __launch_bounds__(NTHREADS, 1)
mhmlp_main_kernel(const float* __restrict__ b2, float* __restrict__ out)
{
    extern __shared__ char smem[];
    const uint32_t sbase = smem_u32(smem);
    float* rowacc = (float*)(smem + OFF_ROWACC);

    const int tid  = threadIdx.x;
    const int lane = tid & 31;
    const int wid  = tid >> 5;
    const int g    = wid >> 2;      // n-half 0/1
    const int w    = wid & 3;
    const int wm   = w >> 1;        // 0..1 : 64-row band
    const int wn   = w & 1;         // 0..1 : 64-col band within half
    const int p    = g * 2 + wn;    // pipelet 0..3
    const int noff = g * 128 + wn * 64;   // pipelet's n-offset in the 256 tile

    const int mt = blockIdx.x;      // 16 (fast dim -> head weights hot in L2)
    const int h  = blockIdx.y;      // 64
    const int m0 = mt * BM;

    if (tid < BM) rowacc[tid] = 0.f;

    const __half* __restrict__ Wh_h = g_Wh + (size_t)h * ND * NHID;
    const float4* __restrict__ pk_h = g_pk4 + (size_t)h * (NHID / 2);

    // ---- hoisted addressing ----
    const uint32_t xmask = ((uint32_t)(lane & 7)) << 4;
    uint32_t baseA[4];
    #pragma unroll
    for (int mi = 0; mi < 4; mi++) {
        int row = wm * 64 + mi * 16 + (lane & 15);
        baseA[mi] = sbase + OFF_A + (uint32_t)(row * 1024);
    }
    uint32_t laneOffA[4];
    #pragma unroll
    for (int ks = 0; ks < 4; ks++)
        laneOffA[ks] = ((uint32_t)(ks * 32 + (lane >> 4) * 16)) ^ xmask;
    uint32_t offBn[4];
    #pragma unroll
    for (int np = 0; np < 4; np++)
        offBn[np] = ((uint32_t)(np * 32 + (lane >> 4) * 16)) ^ xmask;
    const uint32_t rowBbase = (uint32_t)((lane & 15) * 128);

    // staging: pipelet's 64 threads stage 64 rows x 128B
    const int t64 = wm * 32 + lane;       // 0..63 within pipelet
    const int r0 = t64 >> 3;              // 0..7
    const int seg = t64 & 7;              // 0..7
    const uint32_t dstB0 = ((uint32_t)(r0 * 128 + seg * 16)) ^ (((uint32_t)r0) << 4);
    const char* pW = (const char*)Wh_h + (size_t)r0 * NHID * 2
                   + (size_t)noff * 2 + (size_t)seg * 16;
    const uint32_t pB = sbase + OFF_B + (uint32_t)p * PSTRIDE;

    // ---- prologue: stage ALL of A (all 256 threads), own commit group ----
    #pragma unroll
    for (int i = 0; i < 32; i++) {               // 8192 segs of 16B
        int t = tid + i * NTHREADS;
        int r = t >> 6, s = t & 63;
        const void* src = g_Xh + (size_t)(m0 + r) * ND + s * 8;
        uint32_t off = (uint32_t)(r * 1024 + s * 16);
        cp16(sbase + OFF_A + (off ^ (((uint32_t)(r & 7)) << 4)), src);
    }
    cp_commit();     // group [A]

    auto stageB = [&](int cc) {
        const uint32_t base = pB + (uint32_t)(cc % NSTAGE) * BSTG_P + dstB0;
        #pragma unroll
        for (int i = 0; i < 8; i++)              // rows r0 + 8i
            cp16(base + (uint32_t)(i * 1024), pW + (size_t)i * 8 * NHID * 2);
        cp_commit();
        pW += ((cc & 7) == 7) ? WWRAP : (long long)WSTRIDE;
    };

    stageB(0);       // group [B0]
    stageB(1);       // group [B1]
    asm volatile("cp.async.wait_group 2;" ::: "memory");   // A done
    __syncthreads();                                        // A visible to all

    // ---- phase skew: pipelet p delays ~quarter-chunk * p ----
    {
        float dummy = (float)(tid + 1);
        const int iters = p * 172;
        for (int i = 0; i < iters; i++)
            dummy = fmaf(dummy, 0.99999988f, 1.0e-7f);
        if (dummy == 1.2345678e-33f) rowacc[tid & (BM - 1)] = dummy;  // opaque
    }

    float c[4][8][4];
    #pragma unroll
    for (int mi = 0; mi < 4; mi++)
        #pragma unroll
        for (int ni = 0; ni < 8; ni++)
            #pragma unroll
            for (int e = 0; e < 4; e++) c[mi][ni][e] = 0.f;
    float accrow[8] = {0.f,0.f,0.f,0.f,0.f,0.f,0.f,0.f};

    for (int cc = 0; cc < NCHUNK; ++cc) {
        asm volatile("cp.async.wait_group 1;" ::: "memory");
        pbar(1 + p);        // pipelet barrier: chunk cc visible to both warps

        if (cc + 2 < NCHUNK) stageB(cc + 2); else cp_commit();

        const uint32_t ktOff = ((uint32_t)(cc & 7)) << 7;   // kt*128 bytes
        const uint32_t bB = pB + (uint32_t)(cc % NSTAGE) * BSTG_P + rowBbase;

        uint32_t bf[2][8][2];
        {   // preload B slice 0
            #pragma unroll
            for (int np = 0; np < 4; np++) {
                uint32_t ad = bB + offBn[np];
                uint32_t q0, q1, q2, q3;
                asm volatile(
                    "ldmatrix.sync.aligned.m8n8.x4.trans.shared.b16 {%0,%1,%2,%3}, [%4];"
                    : "=r"(q0), "=r"(q1), "=r"(q2), "=r"(q3) : "r"(ad));
                bf[0][2 * np][0] = q0;     bf[0][2 * np][1] = q1;
                bf[0][2 * np + 1][0] = q2; bf[0][2 * np + 1][1] = q3;
            }
        }

        #pragma unroll
        for (int ks = 0; ks < 4; ks++) {
            const int cur = ks & 1, nxt = cur ^ 1;
            uint32_t a[4][4];
            #pragma unroll
            for (int mi = 0; mi < 4; mi++) {
                uint32_t ad = baseA[mi] + laneOffA[ks] + ktOff;
                asm volatile(
                    "ldmatrix.sync.aligned.m8n8.x4.shared.b16 {%0,%1,%2,%3}, [%4];"
                    : "=r"(a[mi][0]), "=r"(a[mi][1]), "=r"(a[mi][2]), "=r"(a[mi][3])
                    : "r"(ad));
            }
            if (ks < 3) {     // prefetch B slice ks+1 under the MMA stream
                #pragma unroll
                for (int np = 0; np < 4; np++) {
                    uint32_t ad = bB + (uint32_t)((ks + 1) * 2048) + offBn[np];
                    uint32_t q0, q1, q2, q3;
                    asm volatile(
                        "ldmatrix.sync.aligned.m8n8.x4.trans.shared.b16 {%0,%1,%2,%3}, [%4];"
                        : "=r"(q0), "=r"(q1), "=r"(q2), "=r"(q3) : "r"(ad));
                    bf[nxt][2 * np][0] = q0;     bf[nxt][2 * np][1] = q1;
                    bf[nxt][2 * np + 1][0] = q2; bf[nxt][2 * np + 1][1] = q3;
                }
            }
            #pragma unroll
            for (int mi = 0; mi < 4; mi++)
                #pragma unroll
                for (int ni = 0; ni < 8; ni++) {
                    asm volatile(
                        "mma.sync.aligned.m16n8k16.row.col.f32.f16.f16.f32 "
                        "{%0,%1,%2,%3}, {%4,%5,%6,%7}, {%8,%9}, {%0,%1,%2,%3};"
                        : "+f"(c[mi][ni][0]), "+f"(c[mi][ni][1]),
                          "+f"(c[mi][ni][2]), "+f"(c[mi][ni][3])
                        : "r"(a[mi][0]), "r"(a[mi][1]), "r"(a[mi][2]), "r"(a[mi][3]),
                          "r"(bf[cur][ni][0]), "r"(bf[cur][ni][1]));
                }
        }

        if ((cc & 7) == 7) {    // K complete -> fused epilogue for this n-tile
            const int nt = cc >> 3;
            #pragma unroll
            for (int ni = 0; ni < 8; ni++) {
                int cidx = nt * 128 + g * 64 + wn * 32 + ni * 4 + (lane & 3);
                float4 pk = __ldg(&pk_h[cidx]);
                #pragma unroll
                for (int mi = 0; mi < 4; mi++)
                    #pragma unroll
                    for (int e = 0; e < 4; e++) {
                        float bia = (e & 1) ? pk.y : pk.x;
                        float w2v = (e & 1) ? pk.w : pk.z;
                        float q = c[mi][ni][e] + bia;
                        accrow[mi * 2 + (e >> 1)] =
                            fmaf(lrelu(q), w2v, accrow[mi * 2 + (e >> 1)]);
                        c[mi][ni][e] = 0.f;
                    }
            }
        }
    }

    // reduce 4 lanes sharing each row, then across warps via smem atomics
    #pragma unroll
    for (int off = 1; off <= 2; off <<= 1)
        #pragma unroll
        for (int j = 0; j < 8; j++)
            accrow[j] += __shfl_xor_sync(0xffffffffu, accrow[j], off);

    __syncthreads();   // rowacc zero-init visible; all pipelets done
    if ((lane & 3) == 0) {
        #pragma unroll
        for (int mi = 0; mi < 4; mi++)
            #pragma unroll
            for (int e2 = 0; e2 < 2; e2++) {
                int row = wm * 64 + mi * 16 + e2 * 8 + (lane >> 2);
                atomicAdd(&rowacc[row], accrow[mi * 2 + e2]);
            }
    }
    __syncthreads();
    if (tid < BM) {
        float v = rowacc[tid] + __ldg(&b2[h]);
        out[(size_t)(m0 + tid) * NH + h] = lrelu(v);
    }
}

// ---------------------------------------------------------------------------
extern "C" void kernel_launch(void* const* d_in, const int* in_sizes, int n_in,
                              void* d_out, int out_size) {
    const float* x  = (const float*)d_in[0];   // [2048, 512]
    const float* W1 = (const float*)d_in[1];   // [64, 512, 2048]
    const float* b1 = (const float*)d_in[2];   // [64, 2048]
    const float* W2 = (const float*)d_in[3];   // [64, 2048]
    const float* b2 = (const float*)d_in[4];   // [64]
    float* out = (float*)d_out;                // [2048, 64]
    (void)in_sizes; (void)n_in; (void)out_size;

    cudaFuncSetAttribute(mhmlp_main_kernel,
                         cudaFuncAttributeMaxDynamicSharedMemorySize, SMEM_DYN);

    convert_all_kernel<<<WBLKS + XBLKS + PBLKS, 256>>>(W1, x, b1, W2);

    dim3 grid(NB / BM, NH);
    mhmlp_main_kernel<<<grid, NTHREADS, SMEM_DYN>>>(b2, out);
}